// round 13
// baseline (speedup 1.0000x reference)
#include <cuda_runtime.h>
#include <math.h>

#define Bv   32
#define Nv   4096
#define Kv   1024
#define Dv   1024
#define Hv   16
#define Lv   2
#define MAXFv 4096

__device__ float g_q    [Bv*2*Dv];
__device__ float g_x    [Bv*2*Dv];
__device__ float g_qkv  [Bv*2*3*Dv];
__device__ float g_attn [Bv*2*Dv];
__device__ float g_qp   [Bv*Dv];
__device__ float g_u    [Bv*Hv*Dv];
__device__ float g_S    [Bv*Hv*Nv];
__device__ float g_wsum [Bv*Hv*Dv];
__device__ float g_wpart[32*Bv*Hv*Dv];
__device__ float g_vo   [Bv*Dv];
__device__ float g_h1   [Bv*2*4*Dv];
__device__ float g_part [Bv*8*Dv];

__device__ __forceinline__ unsigned long long pk2(float a, float b) {
    unsigned long long r;
    asm("mov.b64 %0, {%1, %2};" : "=l"(r) : "f"(a), "f"(b));
    return r;
}
__device__ __forceinline__ void fma2(unsigned long long& d, unsigned long long a, unsigned long long b) {
    asm("fma.rn.f32x2 %0, %1, %2, %3;" : "=l"(d) : "l"(a), "l"(b), "l"(d));
}
__device__ __forceinline__ float sum2(unsigned long long v) {
    float x, y;
    asm("mov.b64 {%0, %1}, %2;" : "=f"(x), "=f"(y) : "l"(v));
    return x + y;
}
__device__ __forceinline__ float2 up2(unsigned long long v) {
    float2 r;
    asm("mov.b64 {%0, %1}, %2;" : "=f"(r.x), "=f"(r.y) : "l"(v));
    return r;
}
__device__ __forceinline__ void cp16(unsigned int s, const void* g) {
    asm volatile("cp.async.ca.shared.global [%0], [%1], 16;" :: "r"(s), "l"(g));
}
#define CP_COMMIT() asm volatile("cp.async.commit_group;")
#define CP_WAIT(n)  asm volatile("cp.async.wait_group %0;" :: "n"(n))

template<int M>
__device__ __forceinline__ void redstep(float* v, int lane) {
#pragma unroll
    for (int i = 0; i < M; i++) {
        float lo = v[i], hj = v[i + M];
        bool hi = (lane & M) != 0;
        float send = hi ? lo : hj;
        float keep = hi ? hj : lo;
        v[i] = keep + __shfl_xor_sync(0xFFFFFFFFu, send, M);
    }
}
__device__ __forceinline__ void red32(float* v, int lane) {
    redstep<16>(v, lane); redstep<8>(v, lane); redstep<4>(v, lane);
    redstep<2>(v, lane);  redstep<1>(v, lane);
}

__global__ void mean_part_kernel(const float* __restrict__ X, float* __restrict__ part) {
    int b = blockIdx.x, ch = blockIdx.y, tid = threadIdx.x;
    const float4* xp = (const float4*)(X + (((size_t)b * Nv + (size_t)ch * 512) << 10)) + tid;
    float4 a = {0.f, 0.f, 0.f, 0.f};
#pragma unroll 8
    for (int i = 0; i < 512; i++) {
        float4 v = xp[(size_t)i * 256];
        a.x += v.x; a.y += v.y; a.z += v.z; a.w += v.w;
    }
    ((float4*)(part + ((size_t)(b * 8 + ch) << 10)))[tid] = a;
}

__global__ void init_q_kernel(const float* __restrict__ part, const float* __restrict__ maxinit,
                              const float* __restrict__ qbase, const float* __restrict__ rolew,
                              const float* __restrict__ timew, const int* __restrict__ fidx,
                              float* __restrict__ q) {
    int b = blockIdx.x, tid = threadIdx.x;
    float4 s = {0.f, 0.f, 0.f, 0.f};
    for (int ch = 0; ch < 8; ch++) {
        float4 v = ((const float4*)(part + ((size_t)(b * 8 + ch) << 10)))[tid];
        s.x += v.x; s.y += v.y; s.z += v.z; s.w += v.w;
    }
    const float inv = 1.0f / (float)Nv;
    int idx = fidx[b];
    idx = idx < 0 ? 0 : (idx > MAXFv - 1 ? MAXFv - 1 : idx);
    float4 te  = ((const float4*)(timew + ((size_t)idx << 10)))[tid];
    float4 qb0 = ((const float4*)qbase)[tid];
    float4 qb1 = ((const float4*)(qbase + Dv))[tid];
    float4 r0  = ((const float4*)rolew)[tid];
    float4 r1  = ((const float4*)(rolew + Dv))[tid];
    float4 mi  = ((const float4*)(maxinit + ((size_t)b << 10)))[tid];
    float4 o0, o1;
    o0.x = s.x * inv + qb0.x + r0.x + te.x;  o0.y = s.y * inv + qb0.y + r0.y + te.y;
    o0.z = s.z * inv + qb0.z + r0.z + te.z;  o0.w = s.w * inv + qb0.w + r0.w + te.w;
    o1.x = mi.x + qb1.x + r1.x + te.x;       o1.y = mi.y + qb1.y + r1.y + te.y;
    o1.z = mi.z + qb1.z + r1.z + te.z;       o1.w = mi.w + qb1.w + r1.w + te.w;
    ((float4*)(q + ((size_t)(b * 2) << 10)))[tid]     = o0;
    ((float4*)(q + ((size_t)(b * 2 + 1) << 10)))[tid] = o1;
}

__global__ void ln_kernel(const float* __restrict__ in, float* __restrict__ out,
                          const float* __restrict__ gg, const float* __restrict__ bb) {
    int row = blockIdx.x, tid = threadIdx.x;
    const float* xp = in + ((size_t)row << 10);
    float4 v = *(const float4*)(xp + tid * 4);
    __shared__ float red[8];
    float s = v.x + v.y + v.z + v.w;
    for (int o = 16; o; o >>= 1) s += __shfl_down_sync(0xFFFFFFFFu, s, o);
    if ((tid & 31) == 0) red[tid >> 5] = s;
    __syncthreads();
    if (tid == 0) { float t = 0; for (int i = 0; i < 8; i++) t += red[i]; red[0] = t; }
    __syncthreads();
    float mean = red[0] * (1.0f / Dv);
    float cx = v.x - mean, cy = v.y - mean, cz = v.z - mean, cw = v.w - mean;
    float qq = cx * cx + cy * cy + cz * cz + cw * cw;
    __syncthreads();
    for (int o = 16; o; o >>= 1) qq += __shfl_down_sync(0xFFFFFFFFu, qq, o);
    if ((tid & 31) == 0) red[tid >> 5] = qq;
    __syncthreads();
    if (tid == 0) { float t = 0; for (int i = 0; i < 8; i++) t += red[i]; red[0] = t; }
    __syncthreads();
    float rstd = rsqrtf(red[0] * (1.0f / Dv) + 1e-5f);
    float4 gv = *(const float4*)(gg + tid * 4);
    float4 bv = *(const float4*)(bb + tid * 4);
    float4 o4;
    o4.x = cx * rstd * gv.x + bv.x;  o4.y = cy * rstd * gv.y + bv.y;
    o4.z = cz * rstd * gv.z + bv.z;  o4.w = cw * rstd * gv.w + bv.w;
    *(float4*)(out + ((size_t)row << 10) + tid * 4) = o4;
}

// gemm5: out[r,c] = bias[c] + sum_k A[r,k]*W[c,k]; cp.async double-buffered W stage.
__global__ void __launch_bounds__(256, 2)
gemm5_kernel(const float* __restrict__ A, int As_,
             const float* __restrict__ W, const float* __restrict__ bias,
             float* __restrict__ out, int Os_, const float* __restrict__ addTo,
             int Cin, int act) {
    __shared__ float ws[2][8 * 128];
    int tid = threadIdx.x;
    int warp = tid >> 5, lane = tid & 31;
    int r0 = blockIdx.y * 32 + warp * 4;
    int cb = blockIdx.x * 8;
    int wc = tid >> 5;
    int wkk = (tid & 31) * 4;
    unsigned int sb = (unsigned int)__cvta_generic_to_shared(ws);
    const float* wsrc = W + (size_t)(cb + wc) * Cin + wkk;

    unsigned long long acc[4][8];
#pragma unroll
    for (int r = 0; r < 4; r++)
#pragma unroll
        for (int cc = 0; cc < 8; cc++) acc[r][cc] = 0ull;

    int nCh = Cin >> 7;
    cp16(sb + (unsigned)(wc * 128 + wkk) * 4u, wsrc);
    CP_COMMIT();
    for (int ch = 0; ch < nCh; ch++) {
        if (ch + 1 < nCh) {
            cp16(sb + (unsigned)(((ch + 1) & 1) * 1024 + wc * 128 + wkk) * 4u,
                 wsrc + (ch + 1) * 128);
            CP_COMMIT();
            CP_WAIT(1);
        } else {
            CP_WAIT(0);
        }
        __syncthreads();
        const float* wbuf = ws[ch & 1];
        int k0 = ch * 128;
        int kk = lane * 4;
        ulonglong2 a2[4];
#pragma unroll
        for (int r = 0; r < 4; r++)
            a2[r] = *(const ulonglong2*)(A + (size_t)(r0 + r) * As_ + k0 + kk);
#pragma unroll
        for (int cc = 0; cc < 8; cc++) {
            ulonglong2 w2 = *(const ulonglong2*)(wbuf + cc * 128 + kk);
#pragma unroll
            for (int r = 0; r < 4; r++) {
                fma2(acc[r][cc], a2[r].x, w2.x);
                fma2(acc[r][cc], a2[r].y, w2.y);
            }
        }
        __syncthreads();
    }
    float v[32];
#pragma unroll
    for (int r = 0; r < 4; r++)
#pragma unroll
        for (int cc = 0; cc < 8; cc++) v[r * 8 + cc] = sum2(acc[r][cc]);
    red32(v, lane);
    int r = r0 + (lane >> 3);
    int c = cb + (lane & 7);
    float val = v[0] + bias[c];
    if (addTo) val += addTo[(size_t)r * Os_ + c];
    if (act) val = 0.5f * val * (1.0f + erff(val * 0.70710678118654752f));
    out[(size_t)r * Os_ + c] = val;
}

__global__ void selfattn_kernel(const float* __restrict__ qkv, float* __restrict__ attn) {
    int bid = blockIdx.x;
    int b = bid >> 4, h = bid & 15;
    int j = threadIdx.x;
    const float* r0 = qkv + (size_t)(b * 2 + 0) * (3 * Dv);
    const float* r1 = qkv + (size_t)(b * 2 + 1) * (3 * Dv);
    int off = h * 64 + j;
    float q0 = r0[off], k0 = r0[Dv + off], v0 = r0[2 * Dv + off];
    float q1 = r1[off], k1 = r1[Dv + off], v1 = r1[2 * Dv + off];
    __shared__ float red[4][64];
    red[0][j] = q0 * k0; red[1][j] = q0 * k1; red[2][j] = q1 * k0; red[3][j] = q1 * k1;
    __syncthreads();
    for (int s = 32; s; s >>= 1) {
        if (j < s) {
#pragma unroll
            for (int r = 0; r < 4; r++) red[r][j] += red[r][j + s];
        }
        __syncthreads();
    }
    float s00 = red[0][0] * 0.125f, s01 = red[1][0] * 0.125f;
    float s10 = red[2][0] * 0.125f, s11 = red[3][0] * 0.125f;
    float m0 = fmaxf(s00, s01), m1 = fmaxf(s10, s11);
    float e00 = __expf(s00 - m0), e01 = __expf(s01 - m0);
    float e10 = __expf(s10 - m1), e11 = __expf(s11 - m1);
    float i0 = 1.0f / (e00 + e01), i1 = 1.0f / (e10 + e11);
    attn[(size_t)(b * 2 + 0) * Dv + off] = (e00 * v0 + e01 * v1) * i0;
    attn[(size_t)(b * 2 + 1) * Dv + off] = (e10 * v0 + e11 * v1) * i1;
}

__global__ void u2_kernel(const float* __restrict__ qp, const float* __restrict__ wk,
                          float* __restrict__ u) {
    int b = blockIdx.x, tid = threadIdx.x;
    int d = (blockIdx.y * 256 + tid) * 2;
    __shared__ unsigned long long qs[1024];
    for (int i = tid; i < 1024; i += 256) {
        float qv = qp[((size_t)b << 10) + i];
        qs[i] = pk2(qv, qv);
    }
    __syncthreads();
#pragma unroll
    for (int h = 0; h < 16; h++) {
        unsigned long long acc = 0ull;
#pragma unroll 8
        for (int jj = 0; jj < 64; jj++) {
            int j = h * 64 + jj;
            unsigned long long w2 = *(const unsigned long long*)(wk + ((size_t)j << 10) + d);
            fma2(acc, w2, qs[j]);
        }
        float2 r = up2(acc);
        float2 o = {r.x * 0.125f, r.y * 0.125f};
        *(float2*)(u + ((size_t)(b * 16 + h) << 10) + d) = o;
    }
}

// scores6: warp = 4 tokens x 4 heads (head-quarter split) -> ~80 regs, 3 blocks/SM.
// Same-token warps (4 head-quarters) share X lines via L1.
__global__ void __launch_bounds__(256, 3)
scores6_kernel(const float* __restrict__ X, const float* __restrict__ u,
               float* __restrict__ S, int n) {
    extern __shared__ float us[];
    int b = blockIdx.x, tid = threadIdx.x;
    {
        const float4* ub = (const float4*)(u + ((size_t)b << 14));
        float4* ud = (float4*)us;
        for (int i = tid; i < 4096; i += 256) ud[i] = ub[i];
    }
    __syncthreads();
    int warp = tid >> 5, lane = tid & 31;
    int hBase = (warp & 3) * 4;          // head quarter
    int tokOff = (warp >> 2) * 4;        // token sub-group: 0 or 4
    int tokBase = blockIdx.y * 128 + tokOff;
    for (int g = 0; g < 16; g++) {
        int t0 = tokBase + g * 8;
        const float* xp = X + (((size_t)b * n + t0) << 10) + lane * 4;
        unsigned long long acc[4][4];
#pragma unroll
        for (int hh = 0; hh < 4; hh++)
#pragma unroll
            for (int t = 0; t < 4; t++) acc[hh][t] = 0ull;
#pragma unroll 4
        for (int q = 0; q < 8; q++) {    // 8 * 32 lanes * 4 floats = 1024 = D
            ulonglong2 x0 = *(const ulonglong2*)(xp + q * 128);
            ulonglong2 x1 = *(const ulonglong2*)(xp + 1024 + q * 128);
            ulonglong2 x2 = *(const ulonglong2*)(xp + 2048 + q * 128);
            ulonglong2 x3 = *(const ulonglong2*)(xp + 3072 + q * 128);
            const float* ubase = us + q * 128 + lane * 4;
#pragma unroll
            for (int hh = 0; hh < 4; hh++) {
                ulonglong2 uq = *(const ulonglong2*)(ubase + ((hBase + hh) << 10));
                fma2(acc[hh][0], x0.x, uq.x); fma2(acc[hh][0], x0.y, uq.y);
                fma2(acc[hh][1], x1.x, uq.x); fma2(acc[hh][1], x1.y, uq.y);
                fma2(acc[hh][2], x2.x, uq.x); fma2(acc[hh][2], x2.y, uq.y);
                fma2(acc[hh][3], x3.x, uq.x); fma2(acc[hh][3], x3.y, uq.y);
            }
        }
        float v[16];
#pragma unroll
        for (int t = 0; t < 4; t++)
#pragma unroll
            for (int hh = 0; hh < 4; hh++) v[t * 4 + hh] = sum2(acc[hh][t]);
        // fold lane halves (xor 16), then 4-step butterfly over 16 values
#pragma unroll
        for (int i = 0; i < 16; i++) v[i] += __shfl_xor_sync(0xFFFFFFFFu, v[i], 16);
        redstep<8>(v, lane); redstep<4>(v, lane); redstep<2>(v, lane); redstep<1>(v, lane);
        // lane l (and l+16) holds output index l&15: t = t0 + (idx>>2), h = hBase + (idx&3)
        if (lane < 16) {
            int t = t0 + (lane >> 2), h = hBase + (lane & 3);
            S[(size_t)(b * 16 + h) * n + t] = v[0];
        }
    }
}

__global__ void softmax_kernel(float* __restrict__ S, int n) {
    int row = blockIdx.x, tid = threadIdx.x;
    float* p = S + (size_t)row * n;
    __shared__ float red[8];
    float m = -1e30f;
    for (int i = tid; i < n; i += 256) m = fmaxf(m, p[i]);
    for (int o = 16; o; o >>= 1) m = fmaxf(m, __shfl_down_sync(0xFFFFFFFFu, m, o));
    if ((tid & 31) == 0) red[tid >> 5] = m;
    __syncthreads();
    if (tid == 0) { float t = red[0]; for (int i = 1; i < 8; i++) t = fmaxf(t, red[i]); red[0] = t; }
    __syncthreads();
    float bm = red[0];
    __syncthreads();
    float s = 0.f;
    for (int i = tid; i < n; i += 256) { float e = __expf(p[i] - bm); p[i] = e; s += e; }
    for (int o = 16; o; o >>= 1) s += __shfl_down_sync(0xFFFFFFFFu, s, o);
    if ((tid & 31) == 0) red[tid >> 5] = s;
    __syncthreads();
    if (tid == 0) { float t = 0; for (int i = 0; i < 8; i++) t += red[i]; red[0] = t; }
    __syncthreads();
    float inv = 1.0f / red[0];
    for (int i = tid; i < n; i += 256) p[i] *= inv;
}

// wsum2: thread owns d-quad; token-split via blockIdx.y.
__global__ void wsum2_kernel(const float* __restrict__ P, const float* __restrict__ X,
                             float* __restrict__ part, int n, int nsplit) {
    __shared__ unsigned long long ps[16 * 128];
    int b = blockIdx.x, tid = threadIdx.x;
    int tokChunk = n / nsplit;
    int tbeg = blockIdx.y * tokChunk;
    unsigned long long acc[16][2];
#pragma unroll
    for (int h = 0; h < 16; h++) { acc[h][0] = 0ull; acc[h][1] = 0ull; }
    for (int base = tbeg; base < tbeg + tokChunk; base += 128) {
        __syncthreads();
#pragma unroll
        for (int i = tid; i < 2048; i += 256) {
            int h = i >> 7, t = i & 127;
            float pv = P[(size_t)(b * 16 + h) * n + base + t];
            ps[i] = pk2(pv, pv);
        }
        __syncthreads();
        const float* xp = X + (((size_t)b * n + base) << 10) + tid * 4;
#pragma unroll 4
        for (int t = 0; t < 128; t++) {
            ulonglong2 x = *(const ulonglong2*)(xp + (size_t)t * 1024);
#pragma unroll
            for (int h = 0; h < 16; h++) {
                unsigned long long pp = ps[(h << 7) + t];
                fma2(acc[h][0], x.x, pp);
                fma2(acc[h][1], x.y, pp);
            }
        }
    }
    float* op = part + (((size_t)(blockIdx.y * Bv + b) * 16) << 10) + tid * 4;
#pragma unroll
    for (int h = 0; h < 16; h++) {
        float2 lo = up2(acc[h][0]), hi = up2(acc[h][1]);
        float4 o = {lo.x, lo.y, hi.x, hi.y};
        *(float4*)(op + ((size_t)h << 10)) = o;
    }
}

__global__ void wreduce_kernel(const float* __restrict__ part, float* __restrict__ out,
                               int nsec) {
    size_t i = (size_t)blockIdx.x * 256 + threadIdx.x;
    float s = 0.f;
    for (int p = 0; p < nsec; p++) s += part[(size_t)p * (Bv * Hv * Dv) + i];
    out[i] = s;
}

__global__ void vproj3_kernel(const float* __restrict__ wsum, const float* __restrict__ wv,
                              const float* __restrict__ bvv, float* __restrict__ vo) {
    int b = blockIdx.x;
    int warp = threadIdx.x >> 5, lane = threadIdx.x & 31;
    int c0 = blockIdx.y * 128 + warp * 16;
    for (int cc = 0; cc < 16; cc++) {
        int c = c0 + cc;
        int h = c >> 6;
        const float* wr = wv + ((size_t)c << 10) + lane * 4;
        const float* ws = wsum + ((size_t)(b * 16 + h) << 10) + lane * 4;
        unsigned long long acc = 0ull;
#pragma unroll
        for (int i = 0; i < 8; i++) {
            ulonglong2 w2 = *(const ulonglong2*)(wr + i * 128);
            ulonglong2 s2 = *(const ulonglong2*)(ws + i * 128);
            fma2(acc, w2.x, s2.x); fma2(acc, w2.y, s2.y);
        }
        float v = sum2(acc);
        for (int o = 16; o; o >>= 1) v += __shfl_xor_sync(0xFFFFFFFFu, v, o);
        if (lane == 0) vo[((size_t)b << 10) + c] = v + bvv[c];
    }
}

extern "C" void kernel_launch(void* const* d_in, const int* in_sizes, int n_in,
                              void* d_out, int out_size) {
    const float* frame  = (const float*)d_in[0];
    const float* kvs    = (const float*)d_in[1];
    const float* maxini = (const float*)d_in[2];
    const float* qbase  = (const float*)d_in[3];
    const float* rolew  = (const float*)d_in[4];
    const float* timew  = (const float*)d_in[5];
    const float* ln1g   = (const float*)d_in[6];
    const float* ln1b   = (const float*)d_in[7];
    const float* sain   = (const float*)d_in[8];
    const float* sainb  = (const float*)d_in[9];
    const float* saout  = (const float*)d_in[10];
    const float* saoutb = (const float*)d_in[11];
    const float* ln2g   = (const float*)d_in[12];
    const float* ln2b   = (const float*)d_in[13];
    const float* cgin   = (const float*)d_in[14];
    const float* cginb  = (const float*)d_in[15];
    const float* cgout  = (const float*)d_in[16];
    const float* cgoutb = (const float*)d_in[17];
    const float* csin   = (const float*)d_in[18];
    const float* csinb  = (const float*)d_in[19];
    const float* csout  = (const float*)d_in[20];
    const float* csoutb = (const float*)d_in[21];
    const float* ln3g   = (const float*)d_in[22];
    const float* ln3b   = (const float*)d_in[23];
    const float* fw1    = (const float*)d_in[24];
    const float* fb1    = (const float*)d_in[25];
    const float* fw2    = (const float*)d_in[26];
    const float* fb2    = (const float*)d_in[27];
    const float* outg   = (const float*)d_in[28];
    const float* outb   = (const float*)d_in[29];
    const int*   fidx   = (const int*)d_in[30];

    float *q, *x, *qkv, *attn, *qp, *u, *S, *wsum, *wpart, *vo, *h1, *part;
    cudaGetSymbolAddress((void**)&q, g_q);
    cudaGetSymbolAddress((void**)&x, g_x);
    cudaGetSymbolAddress((void**)&qkv, g_qkv);
    cudaGetSymbolAddress((void**)&attn, g_attn);
    cudaGetSymbolAddress((void**)&qp, g_qp);
    cudaGetSymbolAddress((void**)&u, g_u);
    cudaGetSymbolAddress((void**)&S, g_S);
    cudaGetSymbolAddress((void**)&wsum, g_wsum);
    cudaGetSymbolAddress((void**)&wpart, g_wpart);
    cudaGetSymbolAddress((void**)&vo, g_vo);
    cudaGetSymbolAddress((void**)&h1, g_h1);
    cudaGetSymbolAddress((void**)&part, g_part);

    cudaFuncSetAttribute(scores6_kernel, cudaFuncAttributeMaxDynamicSharedMemorySize, 65536);

    // my launches 0,1  (harness owns 2 launches before these -> global +2)
    mean_part_kernel<<<dim3(Bv, 8), 256>>>(frame, part);
    init_q_kernel<<<Bv, 256>>>(part, maxini, qbase, rolew, timew, fidx, q);

    bool probed = false;
    for (int l = 0; l < Lv; l++) {
        const float* sain_l   = sain   + (size_t)l * 3 * Dv * Dv;
        const float* sainb_l  = sainb  + (size_t)l * 3 * Dv;
        const float* saout_l  = saout  + (size_t)l * Dv * Dv;
        const float* saoutb_l = saoutb + (size_t)l * Dv;

        ln_kernel<<<64, 256>>>(q, x, ln1g + l * Dv, ln1b + l * Dv);   // my idx 2
        if (!probed) {
            // PROFILING PROBE at my launch index 3 == global index 5 (ncu -s 5 -c 1).
            // Small scores6 on frame (1/8 size); S fully recomputed before any use.
            probed = true;
            scores6_kernel<<<dim3(Bv, 4), 256, 65536>>>(frame, u, S, Nv);
        }
        gemm5_kernel<<<dim3(384, 2), 256>>>(x, Dv, sain_l, sainb_l, qkv, 3 * Dv, nullptr, Dv, 0);
        selfattn_kernel<<<Bv * Hv, 64>>>(qkv, attn);
        gemm5_kernel<<<dim3(128, 2), 256>>>(attn, Dv, saout_l, saoutb_l, q, Dv, q, Dv, 0);

        ln_kernel<<<64, 256>>>(q, x, ln2g + l * Dv, ln2b + l * Dv);

        for (int br = 0; br < 2; br++) {
            const float* Xsrc  = br == 0 ? frame : kvs;
            int          n     = br == 0 ? Nv : Kv;
            int          nsp   = br == 0 ? 16 : 8;
            const float* in_w  = (br == 0 ? cgin  : csin)  + (size_t)l * 3 * Dv * Dv;
            const float* in_b  = (br == 0 ? cginb : csinb) + (size_t)l * 3 * Dv;
            const float* out_w = (br == 0 ? cgout  : csout)  + (size_t)l * Dv * Dv;
            const float* out_b = (br == 0 ? cgoutb : csoutb) + (size_t)l * Dv;
            int tok = br;

            gemm5_kernel<<<dim3(128, 1), 256>>>(x + tok * Dv, 2 * Dv, in_w, in_b, qp, Dv,
                                                nullptr, Dv, 0);
            u2_kernel<<<dim3(Bv, 2), 256>>>(qp, in_w + (size_t)Dv * Dv, u);
            scores6_kernel<<<dim3(Bv, n / 128), 256, 65536>>>(Xsrc, u, S, n);
            softmax_kernel<<<Bv * Hv, 256>>>(S, n);
            wsum2_kernel<<<dim3(Bv, nsp), 256>>>(S, Xsrc, wpart, n, nsp);
            wreduce_kernel<<<Bv * Hv * Dv / 256, 256>>>(wpart, wsum, nsp);
            vproj3_kernel<<<dim3(Bv, 8), 256>>>(wsum, in_w + (size_t)2 * Dv * Dv,
                                                in_b + 2 * Dv, vo);
            gemm5_kernel<<<dim3(128, 1), 256>>>(vo, Dv, out_w, out_b, q + tok * Dv, 2 * Dv,
                                                q + tok * Dv, Dv, 0);
        }

        ln_kernel<<<64, 256>>>(q, x, ln3g + l * Dv, ln3b + l * Dv);
        gemm5_kernel<<<dim3(512, 2), 256>>>(x, Dv, fw1 + (size_t)l * 4 * Dv * Dv,
                                            fb1 + (size_t)l * 4 * Dv, h1, 4 * Dv, nullptr, Dv, 1);
        gemm5_kernel<<<dim3(128, 2), 256>>>(h1, 4 * Dv, fw2 + (size_t)l * Dv * 4 * Dv,
                                            fb2 + (size_t)l * Dv, q, Dv, q, 4 * Dv, 0);
    }

    ln_kernel<<<64, 256>>>(q, (float*)d_out, outg, outb);
}

// round 14
// speedup vs baseline: 1.0698x; 1.0698x over previous
#include <cuda_runtime.h>
#include <math.h>

#define Bv   32
#define Nv   4096
#define Kv   1024
#define Dv   1024
#define Hv   16
#define Lv   2
#define MAXFv 4096

__device__ float g_q    [Bv*2*Dv];
__device__ float g_x    [Bv*2*Dv];
__device__ float g_qkv  [Bv*2*3*Dv];
__device__ float g_attn [Bv*2*Dv];
__device__ float g_qp   [Bv*Dv];
__device__ float g_u    [Bv*Hv*Dv];
__device__ float g_S    [Bv*Hv*Nv];
__device__ float g_wsum [Bv*Hv*Dv];
__device__ float g_wpart[32*Bv*Hv*Dv];
__device__ float g_vo   [Bv*Dv];
__device__ float g_h1   [Bv*2*4*Dv];
__device__ float g_part [Bv*8*Dv];

__device__ __forceinline__ unsigned long long pk2(float a, float b) {
    unsigned long long r;
    asm("mov.b64 %0, {%1, %2};" : "=l"(r) : "f"(a), "f"(b));
    return r;
}
__device__ __forceinline__ void fma2(unsigned long long& d, unsigned long long a, unsigned long long b) {
    asm("fma.rn.f32x2 %0, %1, %2, %3;" : "=l"(d) : "l"(a), "l"(b), "l"(d));
}
__device__ __forceinline__ float sum2(unsigned long long v) {
    float x, y;
    asm("mov.b64 {%0, %1}, %2;" : "=f"(x), "=f"(y) : "l"(v));
    return x + y;
}
__device__ __forceinline__ float2 up2(unsigned long long v) {
    float2 r;
    asm("mov.b64 {%0, %1}, %2;" : "=f"(r.x), "=f"(r.y) : "l"(v));
    return r;
}
__device__ __forceinline__ void cp16(unsigned int s, const void* g) {
    asm volatile("cp.async.ca.shared.global [%0], [%1], 16;" :: "r"(s), "l"(g));
}
#define CP_COMMIT() asm volatile("cp.async.commit_group;")
#define CP_WAIT(n)  asm volatile("cp.async.wait_group %0;" :: "n"(n))

template<int M>
__device__ __forceinline__ void redstep(float* v, int lane) {
#pragma unroll
    for (int i = 0; i < M; i++) {
        float lo = v[i], hj = v[i + M];
        bool hi = (lane & M) != 0;
        float send = hi ? lo : hj;
        float keep = hi ? hj : lo;
        v[i] = keep + __shfl_xor_sync(0xFFFFFFFFu, send, M);
    }
}
__device__ __forceinline__ void red32(float* v, int lane) {
    redstep<16>(v, lane); redstep<8>(v, lane); redstep<4>(v, lane);
    redstep<2>(v, lane);  redstep<1>(v, lane);
}

__global__ void mean_part_kernel(const float* __restrict__ X, float* __restrict__ part) {
    int b = blockIdx.x, ch = blockIdx.y, tid = threadIdx.x;
    const float4* xp = (const float4*)(X + (((size_t)b * Nv + (size_t)ch * 512) << 10)) + tid;
    float4 a = {0.f, 0.f, 0.f, 0.f};
#pragma unroll 8
    for (int i = 0; i < 512; i++) {
        float4 v = xp[(size_t)i * 256];
        a.x += v.x; a.y += v.y; a.z += v.z; a.w += v.w;
    }
    ((float4*)(part + ((size_t)(b * 8 + ch) << 10)))[tid] = a;
}

__global__ void init_q_kernel(const float* __restrict__ part, const float* __restrict__ maxinit,
                              const float* __restrict__ qbase, const float* __restrict__ rolew,
                              const float* __restrict__ timew, const int* __restrict__ fidx,
                              float* __restrict__ q) {
    int b = blockIdx.x, tid = threadIdx.x;
    float4 s = {0.f, 0.f, 0.f, 0.f};
    for (int ch = 0; ch < 8; ch++) {
        float4 v = ((const float4*)(part + ((size_t)(b * 8 + ch) << 10)))[tid];
        s.x += v.x; s.y += v.y; s.z += v.z; s.w += v.w;
    }
    const float inv = 1.0f / (float)Nv;
    int idx = fidx[b];
    idx = idx < 0 ? 0 : (idx > MAXFv - 1 ? MAXFv - 1 : idx);
    float4 te  = ((const float4*)(timew + ((size_t)idx << 10)))[tid];
    float4 qb0 = ((const float4*)qbase)[tid];
    float4 qb1 = ((const float4*)(qbase + Dv))[tid];
    float4 r0  = ((const float4*)rolew)[tid];
    float4 r1  = ((const float4*)(rolew + Dv))[tid];
    float4 mi  = ((const float4*)(maxinit + ((size_t)b << 10)))[tid];
    float4 o0, o1;
    o0.x = s.x * inv + qb0.x + r0.x + te.x;  o0.y = s.y * inv + qb0.y + r0.y + te.y;
    o0.z = s.z * inv + qb0.z + r0.z + te.z;  o0.w = s.w * inv + qb0.w + r0.w + te.w;
    o1.x = mi.x + qb1.x + r1.x + te.x;       o1.y = mi.y + qb1.y + r1.y + te.y;
    o1.z = mi.z + qb1.z + r1.z + te.z;       o1.w = mi.w + qb1.w + r1.w + te.w;
    ((float4*)(q + ((size_t)(b * 2) << 10)))[tid]     = o0;
    ((float4*)(q + ((size_t)(b * 2 + 1) << 10)))[tid] = o1;
}

__global__ void ln_kernel(const float* __restrict__ in, float* __restrict__ out,
                          const float* __restrict__ gg, const float* __restrict__ bb) {
    int row = blockIdx.x, tid = threadIdx.x;
    const float* xp = in + ((size_t)row << 10);
    float4 v = *(const float4*)(xp + tid * 4);
    __shared__ float red[8];
    float s = v.x + v.y + v.z + v.w;
    for (int o = 16; o; o >>= 1) s += __shfl_down_sync(0xFFFFFFFFu, s, o);
    if ((tid & 31) == 0) red[tid >> 5] = s;
    __syncthreads();
    if (tid == 0) { float t = 0; for (int i = 0; i < 8; i++) t += red[i]; red[0] = t; }
    __syncthreads();
    float mean = red[0] * (1.0f / Dv);
    float cx = v.x - mean, cy = v.y - mean, cz = v.z - mean, cw = v.w - mean;
    float qq = cx * cx + cy * cy + cz * cz + cw * cw;
    __syncthreads();
    for (int o = 16; o; o >>= 1) qq += __shfl_down_sync(0xFFFFFFFFu, qq, o);
    if ((tid & 31) == 0) red[tid >> 5] = qq;
    __syncthreads();
    if (tid == 0) { float t = 0; for (int i = 0; i < 8; i++) t += red[i]; red[0] = t; }
    __syncthreads();
    float rstd = rsqrtf(red[0] * (1.0f / Dv) + 1e-5f);
    float4 gv = *(const float4*)(gg + tid * 4);
    float4 bv = *(const float4*)(bb + tid * 4);
    float4 o4;
    o4.x = cx * rstd * gv.x + bv.x;  o4.y = cy * rstd * gv.y + bv.y;
    o4.z = cz * rstd * gv.z + bv.z;  o4.w = cw * rstd * gv.w + bv.w;
    *(float4*)(out + ((size_t)row << 10) + tid * 4) = o4;
}

// gemm5: out[r,c] = bias[c] + sum_k A[r,k]*W[c,k]; cp.async double-buffered W stage.
__global__ void __launch_bounds__(256, 2)
gemm5_kernel(const float* __restrict__ A, int As_,
             const float* __restrict__ W, const float* __restrict__ bias,
             float* __restrict__ out, int Os_, const float* __restrict__ addTo,
             int Cin, int act) {
    __shared__ float ws[2][8 * 128];
    int tid = threadIdx.x;
    int warp = tid >> 5, lane = tid & 31;
    int r0 = blockIdx.y * 32 + warp * 4;
    int cb = blockIdx.x * 8;
    int wc = tid >> 5;
    int wkk = (tid & 31) * 4;
    unsigned int sb = (unsigned int)__cvta_generic_to_shared(ws);
    const float* wsrc = W + (size_t)(cb + wc) * Cin + wkk;

    unsigned long long acc[4][8];
#pragma unroll
    for (int r = 0; r < 4; r++)
#pragma unroll
        for (int cc = 0; cc < 8; cc++) acc[r][cc] = 0ull;

    int nCh = Cin >> 7;
    cp16(sb + (unsigned)(wc * 128 + wkk) * 4u, wsrc);
    CP_COMMIT();
    for (int ch = 0; ch < nCh; ch++) {
        if (ch + 1 < nCh) {
            cp16(sb + (unsigned)(((ch + 1) & 1) * 1024 + wc * 128 + wkk) * 4u,
                 wsrc + (ch + 1) * 128);
            CP_COMMIT();
            CP_WAIT(1);
        } else {
            CP_WAIT(0);
        }
        __syncthreads();
        const float* wbuf = ws[ch & 1];
        int k0 = ch * 128;
        int kk = lane * 4;
        ulonglong2 a2[4];
#pragma unroll
        for (int r = 0; r < 4; r++)
            a2[r] = *(const ulonglong2*)(A + (size_t)(r0 + r) * As_ + k0 + kk);
#pragma unroll
        for (int cc = 0; cc < 8; cc++) {
            ulonglong2 w2 = *(const ulonglong2*)(wbuf + cc * 128 + kk);
#pragma unroll
            for (int r = 0; r < 4; r++) {
                fma2(acc[r][cc], a2[r].x, w2.x);
                fma2(acc[r][cc], a2[r].y, w2.y);
            }
        }
        __syncthreads();
    }
    float v[32];
#pragma unroll
    for (int r = 0; r < 4; r++)
#pragma unroll
        for (int cc = 0; cc < 8; cc++) v[r * 8 + cc] = sum2(acc[r][cc]);
    red32(v, lane);
    int r = r0 + (lane >> 3);
    int c = cb + (lane & 7);
    float val = v[0] + bias[c];
    if (addTo) val += addTo[(size_t)r * Os_ + c];
    if (act) val = 0.5f * val * (1.0f + erff(val * 0.70710678118654752f));
    out[(size_t)r * Os_ + c] = val;
}

__global__ void selfattn_kernel(const float* __restrict__ qkv, float* __restrict__ attn) {
    int bid = blockIdx.x;
    int b = bid >> 4, h = bid & 15;
    int j = threadIdx.x;
    const float* r0 = qkv + (size_t)(b * 2 + 0) * (3 * Dv);
    const float* r1 = qkv + (size_t)(b * 2 + 1) * (3 * Dv);
    int off = h * 64 + j;
    float q0 = r0[off], k0 = r0[Dv + off], v0 = r0[2 * Dv + off];
    float q1 = r1[off], k1 = r1[Dv + off], v1 = r1[2 * Dv + off];
    __shared__ float red[4][64];
    red[0][j] = q0 * k0; red[1][j] = q0 * k1; red[2][j] = q1 * k0; red[3][j] = q1 * k1;
    __syncthreads();
    for (int s = 32; s; s >>= 1) {
        if (j < s) {
#pragma unroll
            for (int r = 0; r < 4; r++) red[r][j] += red[r][j + s];
        }
        __syncthreads();
    }
    float s00 = red[0][0] * 0.125f, s01 = red[1][0] * 0.125f;
    float s10 = red[2][0] * 0.125f, s11 = red[3][0] * 0.125f;
    float m0 = fmaxf(s00, s01), m1 = fmaxf(s10, s11);
    float e00 = __expf(s00 - m0), e01 = __expf(s01 - m0);
    float e10 = __expf(s10 - m1), e11 = __expf(s11 - m1);
    float i0 = 1.0f / (e00 + e01), i1 = 1.0f / (e10 + e11);
    attn[(size_t)(b * 2 + 0) * Dv + off] = (e00 * v0 + e01 * v1) * i0;
    attn[(size_t)(b * 2 + 1) * Dv + off] = (e10 * v0 + e11 * v1) * i1;
}

__global__ void u2_kernel(const float* __restrict__ qp, const float* __restrict__ wk,
                          float* __restrict__ u) {
    int b = blockIdx.x, tid = threadIdx.x;
    int d = (blockIdx.y * 256 + tid) * 2;
    __shared__ unsigned long long qs[1024];
    for (int i = tid; i < 1024; i += 256) {
        float qv = qp[((size_t)b << 10) + i];
        qs[i] = pk2(qv, qv);
    }
    __syncthreads();
#pragma unroll
    for (int h = 0; h < 16; h++) {
        unsigned long long acc = 0ull;
#pragma unroll 8
        for (int jj = 0; jj < 64; jj++) {
            int j = h * 64 + jj;
            unsigned long long w2 = *(const unsigned long long*)(wk + ((size_t)j << 10) + d);
            fma2(acc, w2, qs[j]);
        }
        float2 r = up2(acc);
        float2 o = {r.x * 0.125f, r.y * 0.125f};
        *(float2*)(u + ((size_t)(b * 16 + h) << 10) + d) = o;
    }
}

// scores7: cp.async double-buffered X pipeline.
// smem: u [16*1024] (64KB) + X tile 2 x [8*1024] (2x32KB) = 128KB dynamic.
// Block = (b, 128 tokens); 16 chunks of 8 tokens. Warp = 4 tokens x 4 heads from smem.
__global__ void __launch_bounds__(256)
scores7_kernel(const float* __restrict__ X, const float* __restrict__ u,
               float* __restrict__ S, int n) {
    extern __shared__ float sm[];
    float* us = sm;                    // 16384 floats
    float* xs = sm + 16384;            // 2 * 8192 floats
    int b = blockIdx.x, tid = threadIdx.x;
    {
        const float4* ub = (const float4*)(u + ((size_t)b << 14));
        float4* ud = (float4*)us;
        for (int i = tid; i < 4096; i += 256) ud[i] = ub[i];
    }
    unsigned int sbX = (unsigned int)__cvta_generic_to_shared(xs);
    int tokBlock = blockIdx.y * 128;
    const float* xbase = X + (((size_t)b * n + tokBlock) << 10);

    // prefetch chunk 0 (tokens 0..7 of block): 2048 16B units, 8 per thread
#pragma unroll
    for (int k = 0; k < 8; k++) {
        int i = tid + k * 256;
        cp16(sbX + (unsigned)i * 16u, xbase + ((size_t)i << 2));
    }
    CP_COMMIT();
    __syncthreads();                   // us ready (also covers pipeline init)

    int warp = tid >> 5, lane = tid & 31;
    int hBase = (warp & 3) * 4;        // head quarter
    int tquad = (warp >> 2) * 4;       // token quad within 8-token chunk: 0 or 4

    for (int c = 0; c < 16; c++) {
        if (c + 1 < 16) {
            const float* src = xbase + (((size_t)(c + 1) * 8) << 10);
            unsigned int dst = sbX + (unsigned)(((c + 1) & 1) * 8192) * 4u;
#pragma unroll
            for (int k = 0; k < 8; k++) {
                int i = tid + k * 256;
                cp16(dst + (unsigned)i * 16u, src + ((size_t)i << 2));
            }
            CP_COMMIT();
            CP_WAIT(1);
        } else {
            CP_WAIT(0);
        }
        __syncthreads();               // chunk c visible
        const float* xbuf = xs + (c & 1) * 8192 + tquad * 1024;
        unsigned long long acc[4][4];
#pragma unroll
        for (int hh = 0; hh < 4; hh++)
#pragma unroll
            for (int t = 0; t < 4; t++) acc[hh][t] = 0ull;
#pragma unroll
        for (int q = 0; q < 8; q++) {
            const float* xq = xbuf + q * 128 + lane * 4;
            ulonglong2 x0 = *(const ulonglong2*)(xq);
            ulonglong2 x1 = *(const ulonglong2*)(xq + 1024);
            ulonglong2 x2 = *(const ulonglong2*)(xq + 2048);
            ulonglong2 x3 = *(const ulonglong2*)(xq + 3072);
            const float* ubase = us + q * 128 + lane * 4;
#pragma unroll
            for (int hh = 0; hh < 4; hh++) {
                ulonglong2 uq = *(const ulonglong2*)(ubase + ((hBase + hh) << 10));
                fma2(acc[hh][0], x0.x, uq.x); fma2(acc[hh][0], x0.y, uq.y);
                fma2(acc[hh][1], x1.x, uq.x); fma2(acc[hh][1], x1.y, uq.y);
                fma2(acc[hh][2], x2.x, uq.x); fma2(acc[hh][2], x2.y, uq.y);
                fma2(acc[hh][3], x3.x, uq.x); fma2(acc[hh][3], x3.y, uq.y);
            }
        }
        float v[16];
#pragma unroll
        for (int t = 0; t < 4; t++)
#pragma unroll
            for (int hh = 0; hh < 4; hh++) v[t * 4 + hh] = sum2(acc[hh][t]);
#pragma unroll
        for (int i = 0; i < 16; i++) v[i] += __shfl_xor_sync(0xFFFFFFFFu, v[i], 16);
        redstep<8>(v, lane); redstep<4>(v, lane); redstep<2>(v, lane); redstep<1>(v, lane);
        if (lane < 16) {
            int t = tokBlock + c * 8 + tquad + (lane >> 2);
            int h = hBase + (lane & 3);
            S[(size_t)(b * 16 + h) * n + t] = v[0];
        }
        __syncthreads();               // done reading buf c before it is overwritten
    }
}

__global__ void softmax_kernel(float* __restrict__ S, int n) {
    int row = blockIdx.x, tid = threadIdx.x;
    float* p = S + (size_t)row * n;
    __shared__ float red[8];
    float m = -1e30f;
    for (int i = tid; i < n; i += 256) m = fmaxf(m, p[i]);
    for (int o = 16; o; o >>= 1) m = fmaxf(m, __shfl_down_sync(0xFFFFFFFFu, m, o));
    if ((tid & 31) == 0) red[tid >> 5] = m;
    __syncthreads();
    if (tid == 0) { float t = red[0]; for (int i = 1; i < 8; i++) t = fmaxf(t, red[i]); red[0] = t; }
    __syncthreads();
    float bm = red[0];
    __syncthreads();
    float s = 0.f;
    for (int i = tid; i < n; i += 256) { float e = __expf(p[i] - bm); p[i] = e; s += e; }
    for (int o = 16; o; o >>= 1) s += __shfl_down_sync(0xFFFFFFFFu, s, o);
    if ((tid & 31) == 0) red[tid >> 5] = s;
    __syncthreads();
    if (tid == 0) { float t = 0; for (int i = 0; i < 8; i++) t += red[i]; red[0] = t; }
    __syncthreads();
    float inv = 1.0f / red[0];
    for (int i = tid; i < n; i += 256) p[i] *= inv;
}

// wsum2: thread owns d-quad; token-split via blockIdx.y.
__global__ void wsum2_kernel(const float* __restrict__ P, const float* __restrict__ X,
                             float* __restrict__ part, int n, int nsplit) {
    __shared__ unsigned long long ps[16 * 128];
    int b = blockIdx.x, tid = threadIdx.x;
    int tokChunk = n / nsplit;
    int tbeg = blockIdx.y * tokChunk;
    unsigned long long acc[16][2];
#pragma unroll
    for (int h = 0; h < 16; h++) { acc[h][0] = 0ull; acc[h][1] = 0ull; }
    for (int base = tbeg; base < tbeg + tokChunk; base += 128) {
        __syncthreads();
#pragma unroll
        for (int i = tid; i < 2048; i += 256) {
            int h = i >> 7, t = i & 127;
            float pv = P[(size_t)(b * 16 + h) * n + base + t];
            ps[i] = pk2(pv, pv);
        }
        __syncthreads();
        const float* xp = X + (((size_t)b * n + base) << 10) + tid * 4;
#pragma unroll 4
        for (int t = 0; t < 128; t++) {
            ulonglong2 x = *(const ulonglong2*)(xp + (size_t)t * 1024);
#pragma unroll
            for (int h = 0; h < 16; h++) {
                unsigned long long pp = ps[(h << 7) + t];
                fma2(acc[h][0], x.x, pp);
                fma2(acc[h][1], x.y, pp);
            }
        }
    }
    float* op = part + (((size_t)(blockIdx.y * Bv + b) * 16) << 10) + tid * 4;
#pragma unroll
    for (int h = 0; h < 16; h++) {
        float2 lo = up2(acc[h][0]), hi = up2(acc[h][1]);
        float4 o = {lo.x, lo.y, hi.x, hi.y};
        *(float4*)(op + ((size_t)h << 10)) = o;
    }
}

__global__ void wreduce_kernel(const float* __restrict__ part, float* __restrict__ out,
                               int nsec) {
    size_t i = (size_t)blockIdx.x * 256 + threadIdx.x;
    float s = 0.f;
    for (int p = 0; p < nsec; p++) s += part[(size_t)p * (Bv * Hv * Dv) + i];
    out[i] = s;
}

__global__ void vproj3_kernel(const float* __restrict__ wsum, const float* __restrict__ wv,
                              const float* __restrict__ bvv, float* __restrict__ vo) {
    int b = blockIdx.x;
    int warp = threadIdx.x >> 5, lane = threadIdx.x & 31;
    int c0 = blockIdx.y * 128 + warp * 16;
    for (int cc = 0; cc < 16; cc++) {
        int c = c0 + cc;
        int h = c >> 6;
        const float* wr = wv + ((size_t)c << 10) + lane * 4;
        const float* ws = wsum + ((size_t)(b * 16 + h) << 10) + lane * 4;
        unsigned long long acc = 0ull;
#pragma unroll
        for (int i = 0; i < 8; i++) {
            ulonglong2 w2 = *(const ulonglong2*)(wr + i * 128);
            ulonglong2 s2 = *(const ulonglong2*)(ws + i * 128);
            fma2(acc, w2.x, s2.x); fma2(acc, w2.y, s2.y);
        }
        float v = sum2(acc);
        for (int o = 16; o; o >>= 1) v += __shfl_xor_sync(0xFFFFFFFFu, v, o);
        if (lane == 0) vo[((size_t)b << 10) + c] = v + bvv[c];
    }
}

extern "C" void kernel_launch(void* const* d_in, const int* in_sizes, int n_in,
                              void* d_out, int out_size) {
    const float* frame  = (const float*)d_in[0];
    const float* kvs    = (const float*)d_in[1];
    const float* maxini = (const float*)d_in[2];
    const float* qbase  = (const float*)d_in[3];
    const float* rolew  = (const float*)d_in[4];
    const float* timew  = (const float*)d_in[5];
    const float* ln1g   = (const float*)d_in[6];
    const float* ln1b   = (const float*)d_in[7];
    const float* sain   = (const float*)d_in[8];
    const float* sainb  = (const float*)d_in[9];
    const float* saout  = (const float*)d_in[10];
    const float* saoutb = (const float*)d_in[11];
    const float* ln2g   = (const float*)d_in[12];
    const float* ln2b   = (const float*)d_in[13];
    const float* cgin   = (const float*)d_in[14];
    const float* cginb  = (const float*)d_in[15];
    const float* cgout  = (const float*)d_in[16];
    const float* cgoutb = (const float*)d_in[17];
    const float* csin   = (const float*)d_in[18];
    const float* csinb  = (const float*)d_in[19];
    const float* csout  = (const float*)d_in[20];
    const float* csoutb = (const float*)d_in[21];
    const float* ln3g   = (const float*)d_in[22];
    const float* ln3b   = (const float*)d_in[23];
    const float* fw1    = (const float*)d_in[24];
    const float* fb1    = (const float*)d_in[25];
    const float* fw2    = (const float*)d_in[26];
    const float* fb2    = (const float*)d_in[27];
    const float* outg   = (const float*)d_in[28];
    const float* outb   = (const float*)d_in[29];
    const int*   fidx   = (const int*)d_in[30];

    float *q, *x, *qkv, *attn, *qp, *u, *S, *wsum, *wpart, *vo, *h1, *part;
    cudaGetSymbolAddress((void**)&q, g_q);
    cudaGetSymbolAddress((void**)&x, g_x);
    cudaGetSymbolAddress((void**)&qkv, g_qkv);
    cudaGetSymbolAddress((void**)&attn, g_attn);
    cudaGetSymbolAddress((void**)&qp, g_qp);
    cudaGetSymbolAddress((void**)&u, g_u);
    cudaGetSymbolAddress((void**)&S, g_S);
    cudaGetSymbolAddress((void**)&wsum, g_wsum);
    cudaGetSymbolAddress((void**)&wpart, g_wpart);
    cudaGetSymbolAddress((void**)&vo, g_vo);
    cudaGetSymbolAddress((void**)&h1, g_h1);
    cudaGetSymbolAddress((void**)&part, g_part);

    cudaFuncSetAttribute(scores7_kernel, cudaFuncAttributeMaxDynamicSharedMemorySize, 131072);

    // my launches 0,1  (harness owns 2 launches before these -> global +2)
    mean_part_kernel<<<dim3(Bv, 8), 256>>>(frame, part);
    init_q_kernel<<<Bv, 256>>>(part, maxini, qbase, rolew, timew, fidx, q);

    bool probed = false;
    for (int l = 0; l < Lv; l++) {
        const float* sain_l   = sain   + (size_t)l * 3 * Dv * Dv;
        const float* sainb_l  = sainb  + (size_t)l * 3 * Dv;
        const float* saout_l  = saout  + (size_t)l * Dv * Dv;
        const float* saoutb_l = saoutb + (size_t)l * Dv;

        ln_kernel<<<64, 256>>>(q, x, ln1g + l * Dv, ln1b + l * Dv);   // my idx 2
        if (!probed) {
            // PROFILING PROBE at my launch index 3 == global index 5 (ncu -s 5 -c 1).
            // Small scores7 on frame (1/8 size); S fully recomputed before any use.
            probed = true;
            scores7_kernel<<<dim3(Bv, 4), 256, 131072>>>(frame, u, S, Nv);
        }
        gemm5_kernel<<<dim3(384, 2), 256>>>(x, Dv, sain_l, sainb_l, qkv, 3 * Dv, nullptr, Dv, 0);
        selfattn_kernel<<<Bv * Hv, 64>>>(qkv, attn);
        gemm5_kernel<<<dim3(128, 2), 256>>>(attn, Dv, saout_l, saoutb_l, q, Dv, q, Dv, 0);

        ln_kernel<<<64, 256>>>(q, x, ln2g + l * Dv, ln2b + l * Dv);

        for (int br = 0; br < 2; br++) {
            const float* Xsrc  = br == 0 ? frame : kvs;
            int          n     = br == 0 ? Nv : Kv;
            int          nsp   = br == 0 ? 16 : 8;
            const float* in_w  = (br == 0 ? cgin  : csin)  + (size_t)l * 3 * Dv * Dv;
            const float* in_b  = (br == 0 ? cginb : csinb) + (size_t)l * 3 * Dv;
            const float* out_w = (br == 0 ? cgout  : csout)  + (size_t)l * Dv * Dv;
            const float* out_b = (br == 0 ? cgoutb : csoutb) + (size_t)l * Dv;
            int tok = br;

            gemm5_kernel<<<dim3(128, 1), 256>>>(x + tok * Dv, 2 * Dv, in_w, in_b, qp, Dv,
                                                nullptr, Dv, 0);
            u2_kernel<<<dim3(Bv, 2), 256>>>(qp, in_w + (size_t)Dv * Dv, u);
            scores7_kernel<<<dim3(Bv, n / 128), 256, 131072>>>(Xsrc, u, S, n);
            softmax_kernel<<<Bv * Hv, 256>>>(S, n);
            wsum2_kernel<<<dim3(Bv, nsp), 256>>>(S, Xsrc, wpart, n, nsp);
            wreduce_kernel<<<Bv * Hv * Dv / 256, 256>>>(wpart, wsum, nsp);
            vproj3_kernel<<<dim3(Bv, 8), 256>>>(wsum, in_w + (size_t)2 * Dv * Dv,
                                                in_b + 2 * Dv, vo);
            gemm5_kernel<<<dim3(128, 1), 256>>>(vo, Dv, out_w, out_b, q + tok * Dv, 2 * Dv,
                                                q + tok * Dv, Dv, 0);
        }

        ln_kernel<<<64, 256>>>(q, x, ln3g + l * Dv, ln3b + l * Dv);
        gemm5_kernel<<<dim3(512, 2), 256>>>(x, Dv, fw1 + (size_t)l * 4 * Dv * Dv,
                                            fb1 + (size_t)l * 4 * Dv, h1, 4 * Dv, nullptr, Dv, 1);
        gemm5_kernel<<<dim3(128, 2), 256>>>(h1, 4 * Dv, fw2 + (size_t)l * Dv * 4 * Dv,
                                            fb2 + (size_t)l * Dv, q, Dv, q, 4 * Dv, 0);
    }

    ln_kernel<<<64, 256>>>(q, (float*)d_out, outg, outb);
}

// round 15
// speedup vs baseline: 1.2115x; 1.1325x over previous
#include <cuda_runtime.h>
#include <math.h>

#define Bv   32
#define Nv   4096
#define Kv   1024
#define Dv   1024
#define Hv   16
#define Lv   2
#define MAXFv 4096

__device__ float g_q    [Bv*2*Dv];
__device__ float g_x    [Bv*2*Dv];
__device__ float g_qkv  [Bv*2*3*Dv];
__device__ float g_attn [Bv*2*Dv];
__device__ float g_qp   [Bv*Dv];
__device__ float g_u    [Bv*Hv*Dv];
__device__ float g_S    [Bv*Hv*Nv];
__device__ float g_wsum [Bv*Hv*Dv];
__device__ float g_wpart[32*Bv*Hv*Dv];
__device__ float g_vo   [Bv*Dv];
__device__ float g_h1   [Bv*2*4*Dv];
__device__ float g_part [Bv*8*Dv];

__device__ __forceinline__ unsigned long long pk2(float a, float b) {
    unsigned long long r;
    asm("mov.b64 %0, {%1, %2};" : "=l"(r) : "f"(a), "f"(b));
    return r;
}
__device__ __forceinline__ void fma2(unsigned long long& d, unsigned long long a, unsigned long long b) {
    asm("fma.rn.f32x2 %0, %1, %2, %3;" : "=l"(d) : "l"(a), "l"(b), "l"(d));
}
__device__ __forceinline__ float sum2(unsigned long long v) {
    float x, y;
    asm("mov.b64 {%0, %1}, %2;" : "=f"(x), "=f"(y) : "l"(v));
    return x + y;
}
__device__ __forceinline__ float2 up2(unsigned long long v) {
    float2 r;
    asm("mov.b64 {%0, %1}, %2;" : "=f"(r.x), "=f"(r.y) : "l"(v));
    return r;
}
__device__ __forceinline__ void cp16(unsigned int s, const void* g) {
    asm volatile("cp.async.ca.shared.global [%0], [%1], 16;" :: "r"(s), "l"(g));
}
#define CP_COMMIT() asm volatile("cp.async.commit_group;")
#define CP_WAIT(n)  asm volatile("cp.async.wait_group %0;" :: "n"(n))

template<int M>
__device__ __forceinline__ void redstep(float* v, int lane) {
#pragma unroll
    for (int i = 0; i < M; i++) {
        float lo = v[i], hj = v[i + M];
        bool hi = (lane & M) != 0;
        float send = hi ? lo : hj;
        float keep = hi ? hj : lo;
        v[i] = keep + __shfl_xor_sync(0xFFFFFFFFu, send, M);
    }
}
__device__ __forceinline__ void red32(float* v, int lane) {
    redstep<16>(v, lane); redstep<8>(v, lane); redstep<4>(v, lane);
    redstep<2>(v, lane);  redstep<1>(v, lane);
}

__global__ void mean_part_kernel(const float* __restrict__ X, float* __restrict__ part) {
    int b = blockIdx.x, ch = blockIdx.y, tid = threadIdx.x;
    const float4* xp = (const float4*)(X + (((size_t)b * Nv + (size_t)ch * 512) << 10)) + tid;
    float4 a = {0.f, 0.f, 0.f, 0.f};
#pragma unroll 8
    for (int i = 0; i < 512; i++) {
        float4 v = xp[(size_t)i * 256];
        a.x += v.x; a.y += v.y; a.z += v.z; a.w += v.w;
    }
    ((float4*)(part + ((size_t)(b * 8 + ch) << 10)))[tid] = a;
}

__global__ void init_q_kernel(const float* __restrict__ part, const float* __restrict__ maxinit,
                              const float* __restrict__ qbase, const float* __restrict__ rolew,
                              const float* __restrict__ timew, const int* __restrict__ fidx,
                              float* __restrict__ q) {
    int b = blockIdx.x, tid = threadIdx.x;
    float4 s = {0.f, 0.f, 0.f, 0.f};
    for (int ch = 0; ch < 8; ch++) {
        float4 v = ((const float4*)(part + ((size_t)(b * 8 + ch) << 10)))[tid];
        s.x += v.x; s.y += v.y; s.z += v.z; s.w += v.w;
    }
    const float inv = 1.0f / (float)Nv;
    int idx = fidx[b];
    idx = idx < 0 ? 0 : (idx > MAXFv - 1 ? MAXFv - 1 : idx);
    float4 te  = ((const float4*)(timew + ((size_t)idx << 10)))[tid];
    float4 qb0 = ((const float4*)qbase)[tid];
    float4 qb1 = ((const float4*)(qbase + Dv))[tid];
    float4 r0  = ((const float4*)rolew)[tid];
    float4 r1  = ((const float4*)(rolew + Dv))[tid];
    float4 mi  = ((const float4*)(maxinit + ((size_t)b << 10)))[tid];
    float4 o0, o1;
    o0.x = s.x * inv + qb0.x + r0.x + te.x;  o0.y = s.y * inv + qb0.y + r0.y + te.y;
    o0.z = s.z * inv + qb0.z + r0.z + te.z;  o0.w = s.w * inv + qb0.w + r0.w + te.w;
    o1.x = mi.x + qb1.x + r1.x + te.x;       o1.y = mi.y + qb1.y + r1.y + te.y;
    o1.z = mi.z + qb1.z + r1.z + te.z;       o1.w = mi.w + qb1.w + r1.w + te.w;
    ((float4*)(q + ((size_t)(b * 2) << 10)))[tid]     = o0;
    ((float4*)(q + ((size_t)(b * 2 + 1) << 10)))[tid] = o1;
}

__global__ void ln_kernel(const float* __restrict__ in, float* __restrict__ out,
                          const float* __restrict__ gg, const float* __restrict__ bb) {
    int row = blockIdx.x, tid = threadIdx.x;
    const float* xp = in + ((size_t)row << 10);
    float4 v = *(const float4*)(xp + tid * 4);
    __shared__ float red[8];
    float s = v.x + v.y + v.z + v.w;
    for (int o = 16; o; o >>= 1) s += __shfl_down_sync(0xFFFFFFFFu, s, o);
    if ((tid & 31) == 0) red[tid >> 5] = s;
    __syncthreads();
    if (tid == 0) { float t = 0; for (int i = 0; i < 8; i++) t += red[i]; red[0] = t; }
    __syncthreads();
    float mean = red[0] * (1.0f / Dv);
    float cx = v.x - mean, cy = v.y - mean, cz = v.z - mean, cw = v.w - mean;
    float qq = cx * cx + cy * cy + cz * cz + cw * cw;
    __syncthreads();
    for (int o = 16; o; o >>= 1) qq += __shfl_down_sync(0xFFFFFFFFu, qq, o);
    if ((tid & 31) == 0) red[tid >> 5] = qq;
    __syncthreads();
    if (tid == 0) { float t = 0; for (int i = 0; i < 8; i++) t += red[i]; red[0] = t; }
    __syncthreads();
    float rstd = rsqrtf(red[0] * (1.0f / Dv) + 1e-5f);
    float4 gv = *(const float4*)(gg + tid * 4);
    float4 bv = *(const float4*)(bb + tid * 4);
    float4 o4;
    o4.x = cx * rstd * gv.x + bv.x;  o4.y = cy * rstd * gv.y + bv.y;
    o4.z = cz * rstd * gv.z + bv.z;  o4.w = cw * rstd * gv.w + bv.w;
    *(float4*)(out + ((size_t)row << 10) + tid * 4) = o4;
}

// gemm5: out[r,c] = bias[c] + sum_k A[r,k]*W[c,k]; cp.async double-buffered W stage.
__global__ void __launch_bounds__(256, 2)
gemm5_kernel(const float* __restrict__ A, int As_,
             const float* __restrict__ W, const float* __restrict__ bias,
             float* __restrict__ out, int Os_, const float* __restrict__ addTo,
             int Cin, int act) {
    __shared__ float ws[2][8 * 128];
    int tid = threadIdx.x;
    int warp = tid >> 5, lane = tid & 31;
    int r0 = blockIdx.y * 32 + warp * 4;
    int cb = blockIdx.x * 8;
    int wc = tid >> 5;
    int wkk = (tid & 31) * 4;
    unsigned int sb = (unsigned int)__cvta_generic_to_shared(ws);
    const float* wsrc = W + (size_t)(cb + wc) * Cin + wkk;

    unsigned long long acc[4][8];
#pragma unroll
    for (int r = 0; r < 4; r++)
#pragma unroll
        for (int cc = 0; cc < 8; cc++) acc[r][cc] = 0ull;

    int nCh = Cin >> 7;
    cp16(sb + (unsigned)(wc * 128 + wkk) * 4u, wsrc);
    CP_COMMIT();
    for (int ch = 0; ch < nCh; ch++) {
        if (ch + 1 < nCh) {
            cp16(sb + (unsigned)(((ch + 1) & 1) * 1024 + wc * 128 + wkk) * 4u,
                 wsrc + (ch + 1) * 128);
            CP_COMMIT();
            CP_WAIT(1);
        } else {
            CP_WAIT(0);
        }
        __syncthreads();
        const float* wbuf = ws[ch & 1];
        int k0 = ch * 128;
        int kk = lane * 4;
        ulonglong2 a2[4];
#pragma unroll
        for (int r = 0; r < 4; r++)
            a2[r] = *(const ulonglong2*)(A + (size_t)(r0 + r) * As_ + k0 + kk);
#pragma unroll
        for (int cc = 0; cc < 8; cc++) {
            ulonglong2 w2 = *(const ulonglong2*)(wbuf + cc * 128 + kk);
#pragma unroll
            for (int r = 0; r < 4; r++) {
                fma2(acc[r][cc], a2[r].x, w2.x);
                fma2(acc[r][cc], a2[r].y, w2.y);
            }
        }
        __syncthreads();
    }
    float v[32];
#pragma unroll
    for (int r = 0; r < 4; r++)
#pragma unroll
        for (int cc = 0; cc < 8; cc++) v[r * 8 + cc] = sum2(acc[r][cc]);
    red32(v, lane);
    int r = r0 + (lane >> 3);
    int c = cb + (lane & 7);
    float val = v[0] + bias[c];
    if (addTo) val += addTo[(size_t)r * Os_ + c];
    if (act) val = 0.5f * val * (1.0f + erff(val * 0.70710678118654752f));
    out[(size_t)r * Os_ + c] = val;
}

__global__ void selfattn_kernel(const float* __restrict__ qkv, float* __restrict__ attn) {
    int bid = blockIdx.x;
    int b = bid >> 4, h = bid & 15;
    int j = threadIdx.x;
    const float* r0 = qkv + (size_t)(b * 2 + 0) * (3 * Dv);
    const float* r1 = qkv + (size_t)(b * 2 + 1) * (3 * Dv);
    int off = h * 64 + j;
    float q0 = r0[off], k0 = r0[Dv + off], v0 = r0[2 * Dv + off];
    float q1 = r1[off], k1 = r1[Dv + off], v1 = r1[2 * Dv + off];
    __shared__ float red[4][64];
    red[0][j] = q0 * k0; red[1][j] = q0 * k1; red[2][j] = q1 * k0; red[3][j] = q1 * k1;
    __syncthreads();
    for (int s = 32; s; s >>= 1) {
        if (j < s) {
#pragma unroll
            for (int r = 0; r < 4; r++) red[r][j] += red[r][j + s];
        }
        __syncthreads();
    }
    float s00 = red[0][0] * 0.125f, s01 = red[1][0] * 0.125f;
    float s10 = red[2][0] * 0.125f, s11 = red[3][0] * 0.125f;
    float m0 = fmaxf(s00, s01), m1 = fmaxf(s10, s11);
    float e00 = __expf(s00 - m0), e01 = __expf(s01 - m0);
    float e10 = __expf(s10 - m1), e11 = __expf(s11 - m1);
    float i0 = 1.0f / (e00 + e01), i1 = 1.0f / (e10 + e11);
    attn[(size_t)(b * 2 + 0) * Dv + off] = (e00 * v0 + e01 * v1) * i0;
    attn[(size_t)(b * 2 + 1) * Dv + off] = (e10 * v0 + e11 * v1) * i1;
}

__global__ void u2_kernel(const float* __restrict__ qp, const float* __restrict__ wk,
                          float* __restrict__ u) {
    int b = blockIdx.x, tid = threadIdx.x;
    int d = (blockIdx.y * 256 + tid) * 2;
    __shared__ unsigned long long qs[1024];
    for (int i = tid; i < 1024; i += 256) {
        float qv = qp[((size_t)b << 10) + i];
        qs[i] = pk2(qv, qv);
    }
    __syncthreads();
#pragma unroll
    for (int h = 0; h < 16; h++) {
        unsigned long long acc = 0ull;
#pragma unroll 8
        for (int jj = 0; jj < 64; jj++) {
            int j = h * 64 + jj;
            unsigned long long w2 = *(const unsigned long long*)(wk + ((size_t)j << 10) + d);
            fma2(acc, w2, qs[j]);
        }
        float2 r = up2(acc);
        float2 o = {r.x * 0.125f, r.y * 0.125f};
        *(float2*)(u + ((size_t)(b * 16 + h) << 10) + d) = o;
    }
}

// scores4 (best known): warp = 4 tokens x 8 heads; x via LDG in regs, u via smem.
__global__ void __launch_bounds__(256, 2)
scores4_kernel(const float* __restrict__ X, const float* __restrict__ u,
               float* __restrict__ S, int n) {
    extern __shared__ float us[];
    int b = blockIdx.x, tid = threadIdx.x;
    {
        const float4* ub = (const float4*)(u + ((size_t)b << 14));
        float4* ud = (float4*)us;
        for (int i = tid; i < 4096; i += 256) ud[i] = ub[i];
    }
    __syncthreads();
    int warp = tid >> 5, lane = tid & 31;
    int hBase = (warp & 1) * 8;
    int tokBase = blockIdx.y * 128 + (warp >> 1) * 32;
    for (int g = 0; g < 8; g++) {
        int t0 = tokBase + g * 4;
        const float* xp = X + (((size_t)b * n + t0) << 10) + lane * 4;
        unsigned long long acc[8][4];
#pragma unroll
        for (int hh = 0; hh < 8; hh++)
#pragma unroll
            for (int t = 0; t < 4; t++) acc[hh][t] = 0ull;
#pragma unroll 4
        for (int q = 0; q < 8; q++) {
            ulonglong2 x0 = *(const ulonglong2*)(xp + q * 128);
            ulonglong2 x1 = *(const ulonglong2*)(xp + 1024 + q * 128);
            ulonglong2 x2 = *(const ulonglong2*)(xp + 2048 + q * 128);
            ulonglong2 x3 = *(const ulonglong2*)(xp + 3072 + q * 128);
            const float* ubase = us + q * 128 + lane * 4;
#pragma unroll
            for (int hh = 0; hh < 8; hh++) {
                ulonglong2 uq = *(const ulonglong2*)(ubase + ((hBase + hh) << 10));
                fma2(acc[hh][0], x0.x, uq.x); fma2(acc[hh][0], x0.y, uq.y);
                fma2(acc[hh][1], x1.x, uq.x); fma2(acc[hh][1], x1.y, uq.y);
                fma2(acc[hh][2], x2.x, uq.x); fma2(acc[hh][2], x2.y, uq.y);
                fma2(acc[hh][3], x3.x, uq.x); fma2(acc[hh][3], x3.y, uq.y);
            }
        }
        float v[32];
#pragma unroll
        for (int t = 0; t < 4; t++)
#pragma unroll
            for (int hh = 0; hh < 8; hh++) v[t * 8 + hh] = sum2(acc[hh][t]);
        red32(v, lane);
        int t = t0 + (lane >> 3), h = hBase + (lane & 7);
        S[(size_t)(b * 16 + h) * n + t] = v[0];
    }
}

__global__ void softmax_kernel(float* __restrict__ S, int n) {
    int row = blockIdx.x, tid = threadIdx.x;
    float* p = S + (size_t)row * n;
    __shared__ float red[8];
    float m = -1e30f;
    for (int i = tid; i < n; i += 256) m = fmaxf(m, p[i]);
    for (int o = 16; o; o >>= 1) m = fmaxf(m, __shfl_down_sync(0xFFFFFFFFu, m, o));
    if ((tid & 31) == 0) red[tid >> 5] = m;
    __syncthreads();
    if (tid == 0) { float t = red[0]; for (int i = 1; i < 8; i++) t = fmaxf(t, red[i]); red[0] = t; }
    __syncthreads();
    float bm = red[0];
    __syncthreads();
    float s = 0.f;
    for (int i = tid; i < n; i += 256) { float e = __expf(p[i] - bm); p[i] = e; s += e; }
    for (int o = 16; o; o >>= 1) s += __shfl_down_sync(0xFFFFFFFFu, s, o);
    if ((tid & 31) == 0) red[tid >> 5] = s;
    __syncthreads();
    if (tid == 0) { float t = 0; for (int i = 0; i < 8; i++) t += red[i]; red[0] = t; }
    __syncthreads();
    float inv = 1.0f / red[0];
    for (int i = tid; i < n; i += 256) p[i] *= inv;
}

// wsum4: cp.async double-buffered X pipeline; thread owns d-quad.
// smem: ps u64[16*128] (16KB) + X 2 x [8*1024] floats (64KB) = 80KB -> 2 blocks/SM.
__global__ void __launch_bounds__(256, 2)
wsum4_kernel(const float* __restrict__ P, const float* __restrict__ X,
             float* __restrict__ part, int n, int nsplit) {
    extern __shared__ char smw[];
    unsigned long long* ps = (unsigned long long*)smw;   // 16KB
    float* xs = (float*)(smw + 16384);                   // 2*8192 floats
    int b = blockIdx.x, tid = threadIdx.x;
    int tokChunk = n / nsplit;
    int tbeg = blockIdx.y * tokChunk;
    int nCh = tokChunk >> 3;                             // 8-token chunks
    const float* xbase = X + (((size_t)b * n + tbeg) << 10);
    unsigned int sbX = (unsigned int)__cvta_generic_to_shared(xs);
    unsigned long long acc[16][2];
#pragma unroll
    for (int h = 0; h < 16; h++) { acc[h][0] = 0ull; acc[h][1] = 0ull; }
    // prefetch chunk 0: 8 tokens = 2048 16B units
#pragma unroll
    for (int k = 0; k < 8; k++) {
        int i = tid + k * 256;
        cp16(sbX + (unsigned)i * 16u, xbase + ((size_t)i << 2));
    }
    CP_COMMIT();
    for (int cc = 0; cc < nCh; cc++) {
        if ((cc & 15) == 0) {                            // stage P for next 128 tokens
            __syncthreads();                             // prior reads of ps done
            int base = tbeg + cc * 8;
#pragma unroll
            for (int i = tid; i < 2048; i += 256) {
                int h = i >> 7, t = i & 127;
                float pv = P[(size_t)(b * 16 + h) * n + base + t];
                ps[i] = pk2(pv, pv);
            }
        }
        if (cc + 1 < nCh) {
            const float* src = xbase + (((size_t)(cc + 1) * 8) << 10);
            unsigned int dst = sbX + (unsigned)(((cc + 1) & 1) * 8192) * 4u;
#pragma unroll
            for (int k = 0; k < 8; k++) {
                int i = tid + k * 256;
                cp16(dst + (unsigned)i * 16u, src + ((size_t)i << 2));
            }
            CP_COMMIT();
            CP_WAIT(1);
        } else {
            CP_WAIT(0);
        }
        __syncthreads();                                 // chunk cc + ps visible
        const float* xbuf = xs + (cc & 1) * 8192;
        int tloc = (cc & 15) * 8;
#pragma unroll
        for (int t = 0; t < 8; t++) {
            ulonglong2 x = *(const ulonglong2*)(xbuf + t * 1024 + tid * 4);
#pragma unroll
            for (int h = 0; h < 16; h++) {
                unsigned long long pp = ps[(h << 7) + tloc + t];
                fma2(acc[h][0], x.x, pp);
                fma2(acc[h][1], x.y, pp);
            }
        }
        __syncthreads();                                 // done reading before overwrite
    }
    float* op = part + (((size_t)(blockIdx.y * Bv + b) * 16) << 10) + tid * 4;
#pragma unroll
    for (int h = 0; h < 16; h++) {
        float2 lo = up2(acc[h][0]), hi = up2(acc[h][1]);
        float4 o = {lo.x, lo.y, hi.x, hi.y};
        *(float4*)(op + ((size_t)h << 10)) = o;
    }
}

__global__ void wreduce_kernel(const float* __restrict__ part, float* __restrict__ out,
                               int nsec) {
    size_t i = (size_t)blockIdx.x * 256 + threadIdx.x;
    float s = 0.f;
    for (int p = 0; p < nsec; p++) s += part[(size_t)p * (Bv * Hv * Dv) + i];
    out[i] = s;
}

__global__ void vproj3_kernel(const float* __restrict__ wsum, const float* __restrict__ wv,
                              const float* __restrict__ bvv, float* __restrict__ vo) {
    int b = blockIdx.x;
    int warp = threadIdx.x >> 5, lane = threadIdx.x & 31;
    int c0 = blockIdx.y * 128 + warp * 16;
    for (int cc = 0; cc < 16; cc++) {
        int c = c0 + cc;
        int h = c >> 6;
        const float* wr = wv + ((size_t)c << 10) + lane * 4;
        const float* ws = wsum + ((size_t)(b * 16 + h) << 10) + lane * 4;
        unsigned long long acc = 0ull;
#pragma unroll
        for (int i = 0; i < 8; i++) {
            ulonglong2 w2 = *(const ulonglong2*)(wr + i * 128);
            ulonglong2 s2 = *(const ulonglong2*)(ws + i * 128);
            fma2(acc, w2.x, s2.x); fma2(acc, w2.y, s2.y);
        }
        float v = sum2(acc);
        for (int o = 16; o; o >>= 1) v += __shfl_xor_sync(0xFFFFFFFFu, v, o);
        if (lane == 0) vo[((size_t)b << 10) + c] = v + bvv[c];
    }
}

extern "C" void kernel_launch(void* const* d_in, const int* in_sizes, int n_in,
                              void* d_out, int out_size) {
    const float* frame  = (const float*)d_in[0];
    const float* kvs    = (const float*)d_in[1];
    const float* maxini = (const float*)d_in[2];
    const float* qbase  = (const float*)d_in[3];
    const float* rolew  = (const float*)d_in[4];
    const float* timew  = (const float*)d_in[5];
    const float* ln1g   = (const float*)d_in[6];
    const float* ln1b   = (const float*)d_in[7];
    const float* sain   = (const float*)d_in[8];
    const float* sainb  = (const float*)d_in[9];
    const float* saout  = (const float*)d_in[10];
    const float* saoutb = (const float*)d_in[11];
    const float* ln2g   = (const float*)d_in[12];
    const float* ln2b   = (const float*)d_in[13];
    const float* cgin   = (const float*)d_in[14];
    const float* cginb  = (const float*)d_in[15];
    const float* cgout  = (const float*)d_in[16];
    const float* cgoutb = (const float*)d_in[17];
    const float* csin   = (const float*)d_in[18];
    const float* csinb  = (const float*)d_in[19];
    const float* csout  = (const float*)d_in[20];
    const float* csoutb = (const float*)d_in[21];
    const float* ln3g   = (const float*)d_in[22];
    const float* ln3b   = (const float*)d_in[23];
    const float* fw1    = (const float*)d_in[24];
    const float* fb1    = (const float*)d_in[25];
    const float* fw2    = (const float*)d_in[26];
    const float* fb2    = (const float*)d_in[27];
    const float* outg   = (const float*)d_in[28];
    const float* outb   = (const float*)d_in[29];
    const int*   fidx   = (const int*)d_in[30];

    float *q, *x, *qkv, *attn, *qp, *u, *S, *wsum, *wpart, *vo, *h1, *part;
    cudaGetSymbolAddress((void**)&q, g_q);
    cudaGetSymbolAddress((void**)&x, g_x);
    cudaGetSymbolAddress((void**)&qkv, g_qkv);
    cudaGetSymbolAddress((void**)&attn, g_attn);
    cudaGetSymbolAddress((void**)&qp, g_qp);
    cudaGetSymbolAddress((void**)&u, g_u);
    cudaGetSymbolAddress((void**)&S, g_S);
    cudaGetSymbolAddress((void**)&wsum, g_wsum);
    cudaGetSymbolAddress((void**)&wpart, g_wpart);
    cudaGetSymbolAddress((void**)&vo, g_vo);
    cudaGetSymbolAddress((void**)&h1, g_h1);
    cudaGetSymbolAddress((void**)&part, g_part);

    cudaFuncSetAttribute(scores4_kernel, cudaFuncAttributeMaxDynamicSharedMemorySize, 65536);
    cudaFuncSetAttribute(wsum4_kernel, cudaFuncAttributeMaxDynamicSharedMemorySize, 81920);

    // my launches 0,1  (harness owns 2 launches before these -> global +2)
    mean_part_kernel<<<dim3(Bv, 8), 256>>>(frame, part);
    init_q_kernel<<<Bv, 256>>>(part, maxini, qbase, rolew, timew, fidx, q);

    bool probed = false;
    for (int l = 0; l < Lv; l++) {
        const float* sain_l   = sain   + (size_t)l * 3 * Dv * Dv;
        const float* sainb_l  = sainb  + (size_t)l * 3 * Dv;
        const float* saout_l  = saout  + (size_t)l * Dv * Dv;
        const float* saoutb_l = saoutb + (size_t)l * Dv;

        ln_kernel<<<64, 256>>>(q, x, ln1g + l * Dv, ln1b + l * Dv);   // my idx 2
        if (!probed) {
            // PROFILING PROBE at my idx 3 == global idx 5 (ncu -s 5 -c 1).
            // Full-shape frame wsum4 with whatever S holds (deterministic across
            // replays); wpart is fully rewritten by the real wsum4 calls below
            // before wreduce consumes it, so d_out is unaffected.
            probed = true;
            wsum4_kernel<<<dim3(Bv, 16), 256, 81920>>>(S, frame, wpart, Nv, 16);
        }
        gemm5_kernel<<<dim3(384, 2), 256>>>(x, Dv, sain_l, sainb_l, qkv, 3 * Dv, nullptr, Dv, 0);
        selfattn_kernel<<<Bv * Hv, 64>>>(qkv, attn);
        gemm5_kernel<<<dim3(128, 2), 256>>>(attn, Dv, saout_l, saoutb_l, q, Dv, q, Dv, 0);

        ln_kernel<<<64, 256>>>(q, x, ln2g + l * Dv, ln2b + l * Dv);

        for (int br = 0; br < 2; br++) {
            const float* Xsrc  = br == 0 ? frame : kvs;
            int          n     = br == 0 ? Nv : Kv;
            int          nsp   = br == 0 ? 16 : 8;
            const float* in_w  = (br == 0 ? cgin  : csin)  + (size_t)l * 3 * Dv * Dv;
            const float* in_b  = (br == 0 ? cginb : csinb) + (size_t)l * 3 * Dv;
            const float* out_w = (br == 0 ? cgout  : csout)  + (size_t)l * Dv * Dv;
            const float* out_b = (br == 0 ? cgoutb : csoutb) + (size_t)l * Dv;
            int tok = br;

            gemm5_kernel<<<dim3(128, 1), 256>>>(x + tok * Dv, 2 * Dv, in_w, in_b, qp, Dv,
                                                nullptr, Dv, 0);
            u2_kernel<<<dim3(Bv, 2), 256>>>(qp, in_w + (size_t)Dv * Dv, u);
            scores4_kernel<<<dim3(Bv, n / 128), 256, 65536>>>(Xsrc, u, S, n);
            softmax_kernel<<<Bv * Hv, 256>>>(S, n);
            wsum4_kernel<<<dim3(Bv, nsp), 256, 81920>>>(S, Xsrc, wpart, n, nsp);
            wreduce_kernel<<<Bv * Hv * Dv / 256, 256>>>(wpart, wsum, nsp);
            vproj3_kernel<<<dim3(Bv, 8), 256>>>(wsum, in_w + (size_t)2 * Dv * Dv,
                                                in_b + 2 * Dv, vo);
            gemm5_kernel<<<dim3(128, 1), 256>>>(vo, Dv, out_w, out_b, q + tok * Dv, 2 * Dv,
                                                q + tok * Dv, Dv, 0);
        }

        ln_kernel<<<64, 256>>>(q, x, ln3g + l * Dv, ln3b + l * Dv);
        gemm5_kernel<<<dim3(512, 2), 256>>>(x, Dv, fw1 + (size_t)l * 4 * Dv * Dv,
                                            fb1 + (size_t)l * 4 * Dv, h1, 4 * Dv, nullptr, Dv, 1);
        gemm5_kernel<<<dim3(128, 2), 256>>>(h1, 4 * Dv, fw2 + (size_t)l * Dv * 4 * Dv,
                                            fb2 + (size_t)l * Dv, q, Dv, q, 4 * Dv, 0);
    }

    ln_kernel<<<64, 256>>>(q, (float*)d_out, outg, outb);
}

// round 16
// speedup vs baseline: 2.1026x; 1.7355x over previous
#include <cuda_runtime.h>
#include <math.h>

#define Bv   32
#define Nv   4096
#define Kv   1024
#define Dv   1024
#define Hv   16
#define Lv   2
#define MAXFv 4096

__device__ float g_q    [Bv*2*Dv];
__device__ float g_x    [Bv*2*Dv];
__device__ float g_qkv  [Bv*2*3*Dv];
__device__ float g_attn [Bv*2*Dv];
__device__ float g_qp   [Bv*Dv];
__device__ float g_u    [Bv*Hv*Dv];
__device__ float g_S    [Bv*Hv*Nv];
__device__ float g_wsum [Bv*Hv*Dv];
__device__ float g_wpart[32*Bv*Hv*Dv];
__device__ float g_vo   [Bv*Dv];
__device__ float g_h1   [Bv*2*4*Dv];
__device__ float g_part [Bv*8*Dv];

__device__ __forceinline__ unsigned long long pk2(float a, float b) {
    unsigned long long r;
    asm("mov.b64 %0, {%1, %2};" : "=l"(r) : "f"(a), "f"(b));
    return r;
}
__device__ __forceinline__ void fma2(unsigned long long& d, unsigned long long a, unsigned long long b) {
    asm("fma.rn.f32x2 %0, %1, %2, %3;" : "=l"(d) : "l"(a), "l"(b), "l"(d));
}
__device__ __forceinline__ float sum2(unsigned long long v) {
    float x, y;
    asm("mov.b64 {%0, %1}, %2;" : "=f"(x), "=f"(y) : "l"(v));
    return x + y;
}
__device__ __forceinline__ float2 up2(unsigned long long v) {
    float2 r;
    asm("mov.b64 {%0, %1}, %2;" : "=f"(r.x), "=f"(r.y) : "l"(v));
    return r;
}
__device__ __forceinline__ void cp16(unsigned int s, const void* g) {
    asm volatile("cp.async.ca.shared.global [%0], [%1], 16;" :: "r"(s), "l"(g));
}
#define CP_COMMIT() asm volatile("cp.async.commit_group;")
#define CP_WAIT(n)  asm volatile("cp.async.wait_group %0;" :: "n"(n))

template<int M>
__device__ __forceinline__ void redstep(float* v, int lane) {
#pragma unroll
    for (int i = 0; i < M; i++) {
        float lo = v[i], hj = v[i + M];
        bool hi = (lane & M) != 0;
        float send = hi ? lo : hj;
        float keep = hi ? hj : lo;
        v[i] = keep + __shfl_xor_sync(0xFFFFFFFFu, send, M);
    }
}
__device__ __forceinline__ void red32(float* v, int lane) {
    redstep<16>(v, lane); redstep<8>(v, lane); redstep<4>(v, lane);
    redstep<2>(v, lane);  redstep<1>(v, lane);
}

__global__ void mean_part_kernel(const float* __restrict__ X, float* __restrict__ part) {
    int b = blockIdx.x, ch = blockIdx.y, tid = threadIdx.x;
    const float4* xp = (const float4*)(X + (((size_t)b * Nv + (size_t)ch * 512) << 10)) + tid;
    float4 a = {0.f, 0.f, 0.f, 0.f};
#pragma unroll 8
    for (int i = 0; i < 512; i++) {
        float4 v = xp[(size_t)i * 256];
        a.x += v.x; a.y += v.y; a.z += v.z; a.w += v.w;
    }
    ((float4*)(part + ((size_t)(b * 8 + ch) << 10)))[tid] = a;
}

__global__ void init_q_kernel(const float* __restrict__ part, const float* __restrict__ maxinit,
                              const float* __restrict__ qbase, const float* __restrict__ rolew,
                              const float* __restrict__ timew, const int* __restrict__ fidx,
                              float* __restrict__ q) {
    int b = blockIdx.x, tid = threadIdx.x;
    float4 s = {0.f, 0.f, 0.f, 0.f};
    for (int ch = 0; ch < 8; ch++) {
        float4 v = ((const float4*)(part + ((size_t)(b * 8 + ch) << 10)))[tid];
        s.x += v.x; s.y += v.y; s.z += v.z; s.w += v.w;
    }
    const float inv = 1.0f / (float)Nv;
    int idx = fidx[b];
    idx = idx < 0 ? 0 : (idx > MAXFv - 1 ? MAXFv - 1 : idx);
    float4 te  = ((const float4*)(timew + ((size_t)idx << 10)))[tid];
    float4 qb0 = ((const float4*)qbase)[tid];
    float4 qb1 = ((const float4*)(qbase + Dv))[tid];
    float4 r0  = ((const float4*)rolew)[tid];
    float4 r1  = ((const float4*)(rolew + Dv))[tid];
    float4 mi  = ((const float4*)(maxinit + ((size_t)b << 10)))[tid];
    float4 o0, o1;
    o0.x = s.x * inv + qb0.x + r0.x + te.x;  o0.y = s.y * inv + qb0.y + r0.y + te.y;
    o0.z = s.z * inv + qb0.z + r0.z + te.z;  o0.w = s.w * inv + qb0.w + r0.w + te.w;
    o1.x = mi.x + qb1.x + r1.x + te.x;       o1.y = mi.y + qb1.y + r1.y + te.y;
    o1.z = mi.z + qb1.z + r1.z + te.z;       o1.w = mi.w + qb1.w + r1.w + te.w;
    ((float4*)(q + ((size_t)(b * 2) << 10)))[tid]     = o0;
    ((float4*)(q + ((size_t)(b * 2 + 1) << 10)))[tid] = o1;
}

__global__ void ln_kernel(const float* __restrict__ in, float* __restrict__ out,
                          const float* __restrict__ gg, const float* __restrict__ bb) {
    int row = blockIdx.x, tid = threadIdx.x;
    const float* xp = in + ((size_t)row << 10);
    float4 v = *(const float4*)(xp + tid * 4);
    __shared__ float red[8];
    float s = v.x + v.y + v.z + v.w;
    for (int o = 16; o; o >>= 1) s += __shfl_down_sync(0xFFFFFFFFu, s, o);
    if ((tid & 31) == 0) red[tid >> 5] = s;
    __syncthreads();
    if (tid == 0) { float t = 0; for (int i = 0; i < 8; i++) t += red[i]; red[0] = t; }
    __syncthreads();
    float mean = red[0] * (1.0f / Dv);
    float cx = v.x - mean, cy = v.y - mean, cz = v.z - mean, cw = v.w - mean;
    float qq = cx * cx + cy * cy + cz * cz + cw * cw;
    __syncthreads();
    for (int o = 16; o; o >>= 1) qq += __shfl_down_sync(0xFFFFFFFFu, qq, o);
    if ((tid & 31) == 0) red[tid >> 5] = qq;
    __syncthreads();
    if (tid == 0) { float t = 0; for (int i = 0; i < 8; i++) t += red[i]; red[0] = t; }
    __syncthreads();
    float rstd = rsqrtf(red[0] * (1.0f / Dv) + 1e-5f);
    float4 gv = *(const float4*)(gg + tid * 4);
    float4 bv = *(const float4*)(bb + tid * 4);
    float4 o4;
    o4.x = cx * rstd * gv.x + bv.x;  o4.y = cy * rstd * gv.y + bv.y;
    o4.z = cz * rstd * gv.z + bv.z;  o4.w = cw * rstd * gv.w + bv.w;
    *(float4*)(out + ((size_t)row << 10) + tid * 4) = o4;
}

// gemm5: out[r,c] = bias[c] + sum_k A[r,k]*W[c,k]; cp.async double-buffered W stage.
__global__ void __launch_bounds__(256, 2)
gemm5_kernel(const float* __restrict__ A, int As_,
             const float* __restrict__ W, const float* __restrict__ bias,
             float* __restrict__ out, int Os_, const float* __restrict__ addTo,
             int Cin, int act) {
    __shared__ float ws[2][8 * 128];
    int tid = threadIdx.x;
    int warp = tid >> 5, lane = tid & 31;
    int r0 = blockIdx.y * 32 + warp * 4;
    int cb = blockIdx.x * 8;
    int wc = tid >> 5;
    int wkk = (tid & 31) * 4;
    unsigned int sb = (unsigned int)__cvta_generic_to_shared(ws);
    const float* wsrc = W + (size_t)(cb + wc) * Cin + wkk;

    unsigned long long acc[4][8];
#pragma unroll
    for (int r = 0; r < 4; r++)
#pragma unroll
        for (int cc = 0; cc < 8; cc++) acc[r][cc] = 0ull;

    int nCh = Cin >> 7;
    cp16(sb + (unsigned)(wc * 128 + wkk) * 4u, wsrc);
    CP_COMMIT();
    for (int ch = 0; ch < nCh; ch++) {
        if (ch + 1 < nCh) {
            cp16(sb + (unsigned)(((ch + 1) & 1) * 1024 + wc * 128 + wkk) * 4u,
                 wsrc + (ch + 1) * 128);
            CP_COMMIT();
            CP_WAIT(1);
        } else {
            CP_WAIT(0);
        }
        __syncthreads();
        const float* wbuf = ws[ch & 1];
        int k0 = ch * 128;
        int kk = lane * 4;
        ulonglong2 a2[4];
#pragma unroll
        for (int r = 0; r < 4; r++)
            a2[r] = *(const ulonglong2*)(A + (size_t)(r0 + r) * As_ + k0 + kk);
#pragma unroll
        for (int cc = 0; cc < 8; cc++) {
            ulonglong2 w2 = *(const ulonglong2*)(wbuf + cc * 128 + kk);
#pragma unroll
            for (int r = 0; r < 4; r++) {
                fma2(acc[r][cc], a2[r].x, w2.x);
                fma2(acc[r][cc], a2[r].y, w2.y);
            }
        }
        __syncthreads();
    }
    float v[32];
#pragma unroll
    for (int r = 0; r < 4; r++)
#pragma unroll
        for (int cc = 0; cc < 8; cc++) v[r * 8 + cc] = sum2(acc[r][cc]);
    red32(v, lane);
    int r = r0 + (lane >> 3);
    int c = cb + (lane & 7);
    float val = v[0] + bias[c];
    if (addTo) val += addTo[(size_t)r * Os_ + c];
    if (act) val = 0.5f * val * (1.0f + erff(val * 0.70710678118654752f));
    out[(size_t)r * Os_ + c] = val;
}

__global__ void selfattn_kernel(const float* __restrict__ qkv, float* __restrict__ attn) {
    int bid = blockIdx.x;
    int b = bid >> 4, h = bid & 15;
    int j = threadIdx.x;
    const float* r0 = qkv + (size_t)(b * 2 + 0) * (3 * Dv);
    const float* r1 = qkv + (size_t)(b * 2 + 1) * (3 * Dv);
    int off = h * 64 + j;
    float q0 = r0[off], k0 = r0[Dv + off], v0 = r0[2 * Dv + off];
    float q1 = r1[off], k1 = r1[Dv + off], v1 = r1[2 * Dv + off];
    __shared__ float red[4][64];
    red[0][j] = q0 * k0; red[1][j] = q0 * k1; red[2][j] = q1 * k0; red[3][j] = q1 * k1;
    __syncthreads();
    for (int s = 32; s; s >>= 1) {
        if (j < s) {
#pragma unroll
            for (int r = 0; r < 4; r++) red[r][j] += red[r][j + s];
        }
        __syncthreads();
    }
    float s00 = red[0][0] * 0.125f, s01 = red[1][0] * 0.125f;
    float s10 = red[2][0] * 0.125f, s11 = red[3][0] * 0.125f;
    float m0 = fmaxf(s00, s01), m1 = fmaxf(s10, s11);
    float e00 = __expf(s00 - m0), e01 = __expf(s01 - m0);
    float e10 = __expf(s10 - m1), e11 = __expf(s11 - m1);
    float i0 = 1.0f / (e00 + e01), i1 = 1.0f / (e10 + e11);
    attn[(size_t)(b * 2 + 0) * Dv + off] = (e00 * v0 + e01 * v1) * i0;
    attn[(size_t)(b * 2 + 1) * Dv + off] = (e10 * v0 + e11 * v1) * i1;
}

// u3: 4 independent j-streams per head (MLP=4 instead of a 1024-long serial chain).
__global__ void __launch_bounds__(256, 4)
u3_kernel(const float* __restrict__ qp, const float* __restrict__ wk,
          float* __restrict__ u) {
    int b = blockIdx.x, tid = threadIdx.x;
    int d = (blockIdx.y * 256 + tid) * 2;
    __shared__ unsigned long long qs[1024];
    for (int i = tid; i < 1024; i += 256) {
        float qv = qp[((size_t)b << 10) + i];
        qs[i] = pk2(qv, qv);
    }
    __syncthreads();
#pragma unroll
    for (int h = 0; h < 16; h++) {
        unsigned long long a0 = 0ull, a1 = 0ull, a2 = 0ull, a3 = 0ull;
        int j0 = h * 64;
        const float* w0 = wk + ((size_t)j0 << 10) + d;
#pragma unroll 4
        for (int jj = 0; jj < 16; jj++) {
            unsigned long long w2a = *(const unsigned long long*)(w0 + ((size_t)jj << 10));
            unsigned long long w2b = *(const unsigned long long*)(w0 + ((size_t)(jj + 16) << 10));
            unsigned long long w2c = *(const unsigned long long*)(w0 + ((size_t)(jj + 32) << 10));
            unsigned long long w2d = *(const unsigned long long*)(w0 + ((size_t)(jj + 48) << 10));
            fma2(a0, w2a, qs[j0 + jj]);
            fma2(a1, w2b, qs[j0 + 16 + jj]);
            fma2(a2, w2c, qs[j0 + 32 + jj]);
            fma2(a3, w2d, qs[j0 + 48 + jj]);
        }
        float2 r0 = up2(a0), r1 = up2(a1), r2 = up2(a2), r3 = up2(a3);
        float2 o = {(r0.x + r1.x + r2.x + r3.x) * 0.125f,
                    (r0.y + r1.y + r2.y + r3.y) * 0.125f};
        *(float2*)(u + ((size_t)(b * 16 + h) << 10) + d) = o;
    }
}

// scores4 (best known): warp = 4 tokens x 8 heads; x via LDG in regs, u via smem.
__global__ void __launch_bounds__(256, 2)
scores4_kernel(const float* __restrict__ X, const float* __restrict__ u,
               float* __restrict__ S, int n) {
    extern __shared__ float us[];
    int b = blockIdx.x, tid = threadIdx.x;
    {
        const float4* ub = (const float4*)(u + ((size_t)b << 14));
        float4* ud = (float4*)us;
        for (int i = tid; i < 4096; i += 256) ud[i] = ub[i];
    }
    __syncthreads();
    int warp = tid >> 5, lane = tid & 31;
    int hBase = (warp & 1) * 8;
    int tokBase = blockIdx.y * 128 + (warp >> 1) * 32;
    for (int g = 0; g < 8; g++) {
        int t0 = tokBase + g * 4;
        const float* xp = X + (((size_t)b * n + t0) << 10) + lane * 4;
        unsigned long long acc[8][4];
#pragma unroll
        for (int hh = 0; hh < 8; hh++)
#pragma unroll
            for (int t = 0; t < 4; t++) acc[hh][t] = 0ull;
#pragma unroll 4
        for (int q = 0; q < 8; q++) {
            ulonglong2 x0 = *(const ulonglong2*)(xp + q * 128);
            ulonglong2 x1 = *(const ulonglong2*)(xp + 1024 + q * 128);
            ulonglong2 x2 = *(const ulonglong2*)(xp + 2048 + q * 128);
            ulonglong2 x3 = *(const ulonglong2*)(xp + 3072 + q * 128);
            const float* ubase = us + q * 128 + lane * 4;
#pragma unroll
            for (int hh = 0; hh < 8; hh++) {
                ulonglong2 uq = *(const ulonglong2*)(ubase + ((hBase + hh) << 10));
                fma2(acc[hh][0], x0.x, uq.x); fma2(acc[hh][0], x0.y, uq.y);
                fma2(acc[hh][1], x1.x, uq.x); fma2(acc[hh][1], x1.y, uq.y);
                fma2(acc[hh][2], x2.x, uq.x); fma2(acc[hh][2], x2.y, uq.y);
                fma2(acc[hh][3], x3.x, uq.x); fma2(acc[hh][3], x3.y, uq.y);
            }
        }
        float v[32];
#pragma unroll
        for (int t = 0; t < 4; t++)
#pragma unroll
            for (int hh = 0; hh < 8; hh++) v[t * 8 + hh] = sum2(acc[hh][t]);
        red32(v, lane);
        int t = t0 + (lane >> 3), h = hBase + (lane & 7);
        S[(size_t)(b * 16 + h) * n + t] = v[0];
    }
}

__global__ void softmax_kernel(float* __restrict__ S, int n) {
    int row = blockIdx.x, tid = threadIdx.x;
    float* p = S + (size_t)row * n;
    __shared__ float red[8];
    float m = -1e30f;
    for (int i = tid; i < n; i += 256) m = fmaxf(m, p[i]);
    for (int o = 16; o; o >>= 1) m = fmaxf(m, __shfl_down_sync(0xFFFFFFFFu, m, o));
    if ((tid & 31) == 0) red[tid >> 5] = m;
    __syncthreads();
    if (tid == 0) { float t = red[0]; for (int i = 1; i < 8; i++) t = fmaxf(t, red[i]); red[0] = t; }
    __syncthreads();
    float bm = red[0];
    __syncthreads();
    float s = 0.f;
    for (int i = tid; i < n; i += 256) { float e = __expf(p[i] - bm); p[i] = e; s += e; }
    for (int o = 16; o; o >>= 1) s += __shfl_down_sync(0xFFFFFFFFu, s, o);
    if ((tid & 31) == 0) red[tid >> 5] = s;
    __syncthreads();
    if (tid == 0) { float t = 0; for (int i = 0; i < 8; i++) t += red[i]; red[0] = t; }
    __syncthreads();
    float inv = 1.0f / red[0];
    for (int i = tid; i < n; i += 256) p[i] *= inv;
}

// wsum5: cp.async double-buffered X pipeline; paired-token ps loads (LDS.128).
// smem: ps u64[16*128] (16KB) + X 2 x [8*1024] floats (64KB) = 80KB -> 2 blocks/SM.
__global__ void __launch_bounds__(256, 2)
wsum5_kernel(const float* __restrict__ P, const float* __restrict__ X,
             float* __restrict__ part, int n, int nsplit) {
    extern __shared__ char smw[];
    unsigned long long* ps = (unsigned long long*)smw;   // 16KB
    float* xs = (float*)(smw + 16384);                   // 2*8192 floats
    int b = blockIdx.x, tid = threadIdx.x;
    int tokChunk = n / nsplit;
    int tbeg = blockIdx.y * tokChunk;
    int nCh = tokChunk >> 3;
    const float* xbase = X + (((size_t)b * n + tbeg) << 10);
    unsigned int sbX = (unsigned int)__cvta_generic_to_shared(xs);
    unsigned long long acc[16][2];
#pragma unroll
    for (int h = 0; h < 16; h++) { acc[h][0] = 0ull; acc[h][1] = 0ull; }
#pragma unroll
    for (int k = 0; k < 8; k++) {
        int i = tid + k * 256;
        cp16(sbX + (unsigned)i * 16u, xbase + ((size_t)i << 2));
    }
    CP_COMMIT();
    for (int cc = 0; cc < nCh; cc++) {
        if ((cc & 15) == 0) {
            __syncthreads();
            int base = tbeg + cc * 8;
#pragma unroll
            for (int i = tid; i < 2048; i += 256) {
                int h = i >> 7, t = i & 127;
                float pv = P[(size_t)(b * 16 + h) * n + base + t];
                ps[i] = pk2(pv, pv);
            }
        }
        if (cc + 1 < nCh) {
            const float* src = xbase + (((size_t)(cc + 1) * 8) << 10);
            unsigned int dst = sbX + (unsigned)(((cc + 1) & 1) * 8192) * 4u;
#pragma unroll
            for (int k = 0; k < 8; k++) {
                int i = tid + k * 256;
                cp16(dst + (unsigned)i * 16u, src + ((size_t)i << 2));
            }
            CP_COMMIT();
            CP_WAIT(1);
        } else {
            CP_WAIT(0);
        }
        __syncthreads();
        const float* xbuf = xs + (cc & 1) * 8192;
        int tloc = (cc & 15) * 8;
#pragma unroll
        for (int t = 0; t < 8; t += 2) {
            ulonglong2 x0 = *(const ulonglong2*)(xbuf + t * 1024 + tid * 4);
            ulonglong2 x1 = *(const ulonglong2*)(xbuf + (t + 1) * 1024 + tid * 4);
#pragma unroll
            for (int h = 0; h < 16; h++) {
                ulonglong2 pp = *(const ulonglong2*)(ps + (h << 7) + tloc + t);
                fma2(acc[h][0], x0.x, pp.x);
                fma2(acc[h][1], x0.y, pp.x);
                fma2(acc[h][0], x1.x, pp.y);
                fma2(acc[h][1], x1.y, pp.y);
            }
        }
        __syncthreads();
    }
    float* op = part + (((size_t)(blockIdx.y * Bv + b) * 16) << 10) + tid * 4;
#pragma unroll
    for (int h = 0; h < 16; h++) {
        float2 lo = up2(acc[h][0]), hi = up2(acc[h][1]);
        float4 o = {lo.x, lo.y, hi.x, hi.y};
        *(float4*)(op + ((size_t)h << 10)) = o;
    }
}

__global__ void wreduce_kernel(const float* __restrict__ part, float* __restrict__ out,
                               int nsec) {
    size_t i = (size_t)blockIdx.x * 256 + threadIdx.x;
    float s = 0.f;
    for (int p = 0; p < nsec; p++) s += part[(size_t)p * (Bv * Hv * Dv) + i];
    out[i] = s;
}

__global__ void vproj3_kernel(const float* __restrict__ wsum, const float* __restrict__ wv,
                              const float* __restrict__ bvv, float* __restrict__ vo) {
    int b = blockIdx.x;
    int warp = threadIdx.x >> 5, lane = threadIdx.x & 31;
    int c0 = blockIdx.y * 128 + warp * 16;
    for (int cc = 0; cc < 16; cc++) {
        int c = c0 + cc;
        int h = c >> 6;
        const float* wr = wv + ((size_t)c << 10) + lane * 4;
        const float* ws = wsum + ((size_t)(b * 16 + h) << 10) + lane * 4;
        unsigned long long acc = 0ull;
#pragma unroll
        for (int i = 0; i < 8; i++) {
            ulonglong2 w2 = *(const ulonglong2*)(wr + i * 128);
            ulonglong2 s2 = *(const ulonglong2*)(ws + i * 128);
            fma2(acc, w2.x, s2.x); fma2(acc, w2.y, s2.y);
        }
        float v = sum2(acc);
        for (int o = 16; o; o >>= 1) v += __shfl_xor_sync(0xFFFFFFFFu, v, o);
        if (lane == 0) vo[((size_t)b << 10) + c] = v + bvv[c];
    }
}

extern "C" void kernel_launch(void* const* d_in, const int* in_sizes, int n_in,
                              void* d_out, int out_size) {
    const float* frame  = (const float*)d_in[0];
    const float* kvs    = (const float*)d_in[1];
    const float* maxini = (const float*)d_in[2];
    const float* qbase  = (const float*)d_in[3];
    const float* rolew  = (const float*)d_in[4];
    const float* timew  = (const float*)d_in[5];
    const float* ln1g   = (const float*)d_in[6];
    const float* ln1b   = (const float*)d_in[7];
    const float* sain   = (const float*)d_in[8];
    const float* sainb  = (const float*)d_in[9];
    const float* saout  = (const float*)d_in[10];
    const float* saoutb = (const float*)d_in[11];
    const float* ln2g   = (const float*)d_in[12];
    const float* ln2b   = (const float*)d_in[13];
    const float* cgin   = (const float*)d_in[14];
    const float* cginb  = (const float*)d_in[15];
    const float* cgout  = (const float*)d_in[16];
    const float* cgoutb = (const float*)d_in[17];
    const float* csin   = (const float*)d_in[18];
    const float* csinb  = (const float*)d_in[19];
    const float* csout  = (const float*)d_in[20];
    const float* csoutb = (const float*)d_in[21];
    const float* ln3g   = (const float*)d_in[22];
    const float* ln3b   = (const float*)d_in[23];
    const float* fw1    = (const float*)d_in[24];
    const float* fb1    = (const float*)d_in[25];
    const float* fw2    = (const float*)d_in[26];
    const float* fb2    = (const float*)d_in[27];
    const float* outg   = (const float*)d_in[28];
    const float* outb   = (const float*)d_in[29];
    const int*   fidx   = (const int*)d_in[30];

    float *q, *x, *qkv, *attn, *qp, *u, *S, *wsum, *wpart, *vo, *h1, *part;
    cudaGetSymbolAddress((void**)&q, g_q);
    cudaGetSymbolAddress((void**)&x, g_x);
    cudaGetSymbolAddress((void**)&qkv, g_qkv);
    cudaGetSymbolAddress((void**)&attn, g_attn);
    cudaGetSymbolAddress((void**)&qp, g_qp);
    cudaGetSymbolAddress((void**)&u, g_u);
    cudaGetSymbolAddress((void**)&S, g_S);
    cudaGetSymbolAddress((void**)&wsum, g_wsum);
    cudaGetSymbolAddress((void**)&wpart, g_wpart);
    cudaGetSymbolAddress((void**)&vo, g_vo);
    cudaGetSymbolAddress((void**)&h1, g_h1);
    cudaGetSymbolAddress((void**)&part, g_part);

    cudaFuncSetAttribute(scores4_kernel, cudaFuncAttributeMaxDynamicSharedMemorySize, 65536);
    cudaFuncSetAttribute(wsum5_kernel, cudaFuncAttributeMaxDynamicSharedMemorySize, 81920);

    mean_part_kernel<<<dim3(Bv, 8), 256>>>(frame, part);
    init_q_kernel<<<Bv, 256>>>(part, maxini, qbase, rolew, timew, fidx, q);

    for (int l = 0; l < Lv; l++) {
        const float* sain_l   = sain   + (size_t)l * 3 * Dv * Dv;
        const float* sainb_l  = sainb  + (size_t)l * 3 * Dv;
        const float* saout_l  = saout  + (size_t)l * Dv * Dv;
        const float* saoutb_l = saoutb + (size_t)l * Dv;

        ln_kernel<<<64, 256>>>(q, x, ln1g + l * Dv, ln1b + l * Dv);
        gemm5_kernel<<<dim3(384, 2), 256>>>(x, Dv, sain_l, sainb_l, qkv, 3 * Dv, nullptr, Dv, 0);
        selfattn_kernel<<<Bv * Hv, 64>>>(qkv, attn);
        gemm5_kernel<<<dim3(128, 2), 256>>>(attn, Dv, saout_l, saoutb_l, q, Dv, q, Dv, 0);

        ln_kernel<<<64, 256>>>(q, x, ln2g + l * Dv, ln2b + l * Dv);

        for (int br = 0; br < 2; br++) {
            const float* Xsrc  = br == 0 ? frame : kvs;
            int          n     = br == 0 ? Nv : Kv;
            int          nsp   = br == 0 ? 16 : 8;
            const float* in_w  = (br == 0 ? cgin  : csin)  + (size_t)l * 3 * Dv * Dv;
            const float* in_b  = (br == 0 ? cginb : csinb) + (size_t)l * 3 * Dv;
            const float* out_w = (br == 0 ? cgout  : csout)  + (size_t)l * Dv * Dv;
            const float* out_b = (br == 0 ? cgoutb : csoutb) + (size_t)l * Dv;
            int tok = br;

            gemm5_kernel<<<dim3(128, 1), 256>>>(x + tok * Dv, 2 * Dv, in_w, in_b, qp, Dv,
                                                nullptr, Dv, 0);
            u3_kernel<<<dim3(Bv, 2), 256>>>(qp, in_w + (size_t)Dv * Dv, u);
            scores4_kernel<<<dim3(Bv, n / 128), 256, 65536>>>(Xsrc, u, S, n);
            softmax_kernel<<<Bv * Hv, 256>>>(S, n);
            wsum5_kernel<<<dim3(Bv, nsp), 256, 81920>>>(S, Xsrc, wpart, n, nsp);
            wreduce_kernel<<<Bv * Hv * Dv / 256, 256>>>(wpart, wsum, nsp);
            vproj3_kernel<<<dim3(Bv, 8), 256>>>(wsum, in_w + (size_t)2 * Dv * Dv,
                                                in_b + 2 * Dv, vo);
            gemm5_kernel<<<dim3(128, 1), 256>>>(vo, Dv, out_w, out_b, q + tok * Dv, 2 * Dv,
                                                q + tok * Dv, Dv, 0);
        }

        ln_kernel<<<64, 256>>>(q, x, ln3g + l * Dv, ln3b + l * Dv);
        gemm5_kernel<<<dim3(512, 2), 256>>>(x, Dv, fw1 + (size_t)l * 4 * Dv * Dv,
                                            fb1 + (size_t)l * 4 * Dv, h1, 4 * Dv, nullptr, Dv, 1);
        gemm5_kernel<<<dim3(128, 2), 256>>>(h1, 4 * Dv, fw2 + (size_t)l * Dv * 4 * Dv,
                                            fb2 + (size_t)l * Dv, q, Dv, q, 4 * Dv, 0);
    }

    ln_kernel<<<64, 256>>>(q, (float*)d_out, outg, outb);
}